// round 4
// baseline (speedup 1.0000x reference)
#include <cuda_runtime.h>
#include <math.h>

#define BCD 8
#define SD  4096
#define DD  1024
#define ED  160
#define HD  16
#define DHD 64
#define CD  4
#define BD  2

// ---------------- scratch (static device globals; no allocation) ----------------
__device__ float g_Q[BCD * SD * DD];      // 128 MB
__device__ float g_attn[BCD * SD * DD];   // 128 MB
__device__ float g_K[BCD * ED * DD];      // 5 MB
__device__ float g_V[BCD * ED * DD];      // 5 MB
__device__ float g_pooled[BCD * HD * SD]; // 2 MB
__device__ float g_wp[BCD * HD * SD];     // 2 MB

// ---------------- tf32 tensor-core GEMM: C = A[MxK] @ B[KxN] ------------------
// Optional A-row/col-group scaling (wp) and epilogue (+bias+resid).
// block 256 thr = 8 warps (4 in M x 2 in N), CTA tile 128x128, K-step 16,
// double-buffered smem, warp tile 32x64 via mma.sync.m16n8k8.tf32.
#define TFPAD 136

__device__ __forceinline__ float tf32r(float x) {
    asm("cvt.rna.tf32.f32 %0, %1;" : "=f"(x) : "f"(x));
    return x;
}

__device__ __forceinline__ void mma_tf32(float* c, const float* a, const float* b) {
    asm volatile(
        "mma.sync.aligned.m16n8k8.row.col.f32.tf32.tf32.f32 "
        "{%0,%1,%2,%3}, {%4,%5,%6,%7}, {%8,%9}, {%0,%1,%2,%3};\n"
        : "+f"(c[0]), "+f"(c[1]), "+f"(c[2]), "+f"(c[3])
        : "r"(__float_as_uint(a[0])), "r"(__float_as_uint(a[1])),
          "r"(__float_as_uint(a[2])), "r"(__float_as_uint(a[3])),
          "r"(__float_as_uint(b[0])), "r"(__float_as_uint(b[1])));
}

// wp lookup for A element at (global row, global k): w = wp[(bc*HD + h)*SD + s]
// row = bc*SD + s  (M = BCD*SD), h = k >> 6.
__device__ __forceinline__ float wp_of(const float* __restrict__ wp, int row, int k) {
    int bc = row >> 12;            // row / 4096
    int s  = row & 4095;
    int h  = k >> 6;
    return wp[((size_t)bc * HD + h) * SD + s];
}

template <bool EPI>
__global__ __launch_bounds__(256)
void tgemm_kernel(const float* __restrict__ A, const float* __restrict__ B,
                  float* __restrict__ C, int M, int N, int K,
                  const float* __restrict__ bias, const float* __restrict__ resid,
                  const float* __restrict__ wscale)
{
    __shared__ float As[2][16][TFPAD];   // As[buf][k][m]  (A tile transposed)
    __shared__ float Bs[2][16][TFPAD];   // Bs[buf][k][n]

    const int tid  = threadIdx.x;
    const int lane = tid & 31;
    const int warp = tid >> 5;
    const int warp_m = warp & 3;
    const int warp_n = warp >> 2;
    const int bm = blockIdx.y * 128;
    const int bn = blockIdx.x * 128;

    const int arow = tid >> 2;           // 0..63 (+64)
    const int acol = (tid & 3) * 4;
    const int brow = tid >> 5;           // 0..7 (+8)
    const int bcol = (tid & 31) * 4;

    float acc[2][8][4];
#pragma unroll
    for (int mi = 0; mi < 2; mi++)
#pragma unroll
        for (int ni = 0; ni < 8; ni++)
#pragma unroll
            for (int r = 0; r < 4; r++) acc[mi][ni][r] = 0.f;

    // ---- load first tile into buffer 0 ----
#pragma unroll
    for (int i = 0; i < 2; i++) {
        int r = arow + i * 64;
        float4 a = *(const float4*)&A[(size_t)(bm + r) * K + acol];
        float w = EPI ? wp_of(wscale, bm + r, acol) : 1.f;
        As[0][acol + 0][r] = tf32r(a.x * w);
        As[0][acol + 1][r] = tf32r(a.y * w);
        As[0][acol + 2][r] = tf32r(a.z * w);
        As[0][acol + 3][r] = tf32r(a.w * w);
    }
#pragma unroll
    for (int i = 0; i < 2; i++) {
        int r = brow + i * 8;
        float4 b = *(const float4*)&B[(size_t)r * N + bn + bcol];
        float4 t;
        t.x = tf32r(b.x); t.y = tf32r(b.y); t.z = tf32r(b.z); t.w = tf32r(b.w);
        *(float4*)&Bs[0][r][bcol] = t;
    }
    __syncthreads();

    int buf = 0;
    for (int k0 = 0; k0 < K; k0 += 16) {
        const bool more = (k0 + 16) < K;
        float4 pa[2], pb[2];
        float pw[2];
        if (more) {
#pragma unroll
            for (int i = 0; i < 2; i++) {
                int r = arow + i * 64;
                pa[i] = *(const float4*)&A[(size_t)(bm + r) * K + k0 + 16 + acol];
                if (EPI) pw[i] = wp_of(wscale, bm + r, k0 + 16 + acol);
            }
#pragma unroll
            for (int i = 0; i < 2; i++) {
                int r = brow + i * 8;
                pb[i] = *(const float4*)&B[(size_t)(k0 + 16 + r) * N + bn + bcol];
            }
        }

        // ---- compute on current buffer: 2 k-slices of 8 ----
#pragma unroll
        for (int kk = 0; kk < 2; kk++) {
            const int kA0 = kk * 8 + (lane & 3);
            const int kA1 = kA0 + 4;
            const int m0 = warp_m * 32 + (lane >> 2);
            const int n0 = warp_n * 64 + (lane >> 2);

            float a[2][4];
#pragma unroll
            for (int mi = 0; mi < 2; mi++) {
                int m = m0 + mi * 16;
                a[mi][0] = As[buf][kA0][m];
                a[mi][1] = As[buf][kA0][m + 8];
                a[mi][2] = As[buf][kA1][m];
                a[mi][3] = As[buf][kA1][m + 8];
            }
            float b[8][2];
#pragma unroll
            for (int ni = 0; ni < 8; ni++) {
                b[ni][0] = Bs[buf][kA0][n0 + ni * 8];
                b[ni][1] = Bs[buf][kA1][n0 + ni * 8];
            }
#pragma unroll
            for (int mi = 0; mi < 2; mi++)
#pragma unroll
                for (int ni = 0; ni < 8; ni++)
                    mma_tf32(acc[mi][ni], a[mi], b[ni]);
        }

        if (more) {
            int nb = buf ^ 1;
#pragma unroll
            for (int i = 0; i < 2; i++) {
                int r = arow + i * 64;
                float w = EPI ? pw[i] : 1.f;
                As[nb][acol + 0][r] = tf32r(pa[i].x * w);
                As[nb][acol + 1][r] = tf32r(pa[i].y * w);
                As[nb][acol + 2][r] = tf32r(pa[i].z * w);
                As[nb][acol + 3][r] = tf32r(pa[i].w * w);
            }
#pragma unroll
            for (int i = 0; i < 2; i++) {
                int r = brow + i * 8;
                float4 t;
                t.x = tf32r(pb[i].x); t.y = tf32r(pb[i].y);
                t.z = tf32r(pb[i].z); t.w = tf32r(pb[i].w);
                *(float4*)&Bs[nb][r][bcol] = t;
            }
            __syncthreads();
            buf = nb;
        }
    }

    // ---- epilogue ----
    const int mrow = bm + warp_m * 32 + (lane >> 2);
    const int ncol = bn + warp_n * 64 + 2 * (lane & 3);
#pragma unroll
    for (int mi = 0; mi < 2; mi++) {
#pragma unroll
        for (int ni = 0; ni < 8; ni++) {
            int r0 = mrow + mi * 16;
            int c  = ncol + ni * 8;
            float2 v0 = make_float2(acc[mi][ni][0], acc[mi][ni][1]);
            float2 v1 = make_float2(acc[mi][ni][2], acc[mi][ni][3]);
            size_t i0 = (size_t)r0 * N + c;
            size_t i1 = (size_t)(r0 + 8) * N + c;
            if (EPI) {
                float b0 = bias[c], b1 = bias[c + 1];
                const float2 r0v = *(const float2*)&resid[i0];
                const float2 r1v = *(const float2*)&resid[i1];
                v0.x += b0 + r0v.x; v0.y += b1 + r0v.y;
                v1.x += b0 + r1v.x; v1.y += b1 + r1v.y;
            }
            *(float2*)&C[i0] = v0;
            *(float2*)&C[i1] = v1;
        }
    }
}

// ---------------- fused attention: scores -> softmax+pooled -> PV ----------------
// grid: (S/64, H, BC), block: 256 threads
#define QS_STRIDE 65
#define KS_STRIDE 65
#define VS_STRIDE 64
#define SS_STRIDE 161
#define QS_FLOATS (64 * QS_STRIDE)
#define KS_FLOATS (ED * KS_STRIDE)
#define VS_FLOATS (ED * VS_STRIDE)
#define SS_FLOATS (64 * SS_STRIDE)
#define ATTN_SMEM_BYTES ((QS_FLOATS + KS_FLOATS + VS_FLOATS + SS_FLOATS) * 4)

__global__ void attn_kernel(const float* __restrict__ Q, const float* __restrict__ Kc,
                            const float* __restrict__ Vc, float* __restrict__ Ou,
                            float* __restrict__ pooled)
{
    extern __shared__ float sm[];
    float* Qs = sm;
    float* Ks = Qs + QS_FLOATS;
    float* Vs = Ks + KS_FLOATS;
    float* Ss = Vs + VS_FLOATS;

    const int tid = threadIdx.x;
    const int s0 = blockIdx.x * 64;
    const int h  = blockIdx.y;
    const int bc = blockIdx.z;

    {
        const size_t qbase = ((size_t)bc * SD + s0) * DD + h * DHD;
#pragma unroll
        for (int i = 0; i < 4; i++) {
            int idx = tid + 256 * i;
            int r = idx >> 4;
            int c = (idx & 15) * 4;
            float4 v = *(const float4*)&Q[qbase + (size_t)r * DD + c];
            Qs[r * QS_STRIDE + c + 0] = v.x;
            Qs[r * QS_STRIDE + c + 1] = v.y;
            Qs[r * QS_STRIDE + c + 2] = v.z;
            Qs[r * QS_STRIDE + c + 3] = v.w;
        }
    }
    {
        const size_t kbase = ((size_t)bc * ED) * DD + h * DHD;
#pragma unroll
        for (int i = 0; i < 10; i++) {
            int idx = tid + 256 * i;
            int r = idx >> 4;
            int c = (idx & 15) * 4;
            float4 kv = *(const float4*)&Kc[kbase + (size_t)r * DD + c];
            Ks[r * KS_STRIDE + c + 0] = kv.x;
            Ks[r * KS_STRIDE + c + 1] = kv.y;
            Ks[r * KS_STRIDE + c + 2] = kv.z;
            Ks[r * KS_STRIDE + c + 3] = kv.w;
            float4 vv = *(const float4*)&Vc[kbase + (size_t)r * DD + c];
            *(float4*)&Vs[r * VS_STRIDE + c] = vv;
        }
    }
    __syncthreads();

    {
        const int ty = tid >> 4, tx = tid & 15;
        float acc[4][10];
#pragma unroll
        for (int i = 0; i < 4; i++)
#pragma unroll
            for (int j = 0; j < 10; j++) acc[i][j] = 0.f;

#pragma unroll 8
        for (int d = 0; d < DHD; d++) {
            float a[4], b[10];
#pragma unroll
            for (int i = 0; i < 4; i++) a[i] = Qs[(ty * 4 + i) * QS_STRIDE + d];
#pragma unroll
            for (int j = 0; j < 10; j++) b[j] = Ks[(tx * 10 + j) * KS_STRIDE + d];
#pragma unroll
            for (int i = 0; i < 4; i++)
#pragma unroll
                for (int j = 0; j < 10; j++) acc[i][j] += a[i] * b[j];
        }
        const float scale = 0.125f;
#pragma unroll
        for (int i = 0; i < 4; i++)
#pragma unroll
            for (int j = 0; j < 10; j++)
                Ss[(ty * 4 + i) * SS_STRIDE + tx * 10 + j] = acc[i][j] * scale;
    }
    __syncthreads();

    if (tid < 64) {
        float* row = Ss + tid * SS_STRIDE;
        float mx = -1e30f, sraw = 0.f;
#pragma unroll 8
        for (int t = 0; t < ED; t++) {
            float v = row[t];
            sraw += v;
            mx = fmaxf(mx, v);
        }
        float se = 0.f;
#pragma unroll 8
        for (int t = 0; t < ED; t++) {
            float e = __expf(row[t] - mx);
            row[t] = e;
            se += e;
        }
        float inv = 1.f / se;
#pragma unroll 8
        for (int t = 0; t < ED; t++) row[t] *= inv;
        pooled[((size_t)bc * HD + h) * SD + s0 + tid] = sraw * (1.f / 160.f);
    }
    __syncthreads();

    {
        const int ty = tid >> 4, tx = tid & 15;
        float o[4][4];
#pragma unroll
        for (int i = 0; i < 4; i++)
#pragma unroll
            for (int j = 0; j < 4; j++) o[i][j] = 0.f;

#pragma unroll 8
        for (int t = 0; t < ED; t++) {
            float a[4], b[4];
#pragma unroll
            for (int i = 0; i < 4; i++) a[i] = Ss[(ty * 4 + i) * SS_STRIDE + t];
#pragma unroll
            for (int j = 0; j < 4; j++) b[j] = Vs[t * VS_STRIDE + tx * 4 + j];
#pragma unroll
            for (int i = 0; i < 4; i++)
#pragma unroll
                for (int j = 0; j < 4; j++) o[i][j] += a[i] * b[j];
        }
        const size_t obase = ((size_t)bc * SD + s0) * DD + h * DHD;
#pragma unroll
        for (int i = 0; i < 4; i++)
            *(float4*)&Ou[obase + (size_t)(ty * 4 + i) * DD + tx * 4] = *(float4*)&o[i][0];
    }
}

// ---------------- component softmax over pooled -> wp ----------------
__global__ void wp_kernel(const float* __restrict__ pooled, float* __restrict__ wp)
{
    int idx = blockIdx.x * blockDim.x + threadIdx.x;
    if (idx >= BD * HD * SD) return;
    int b = idx / (HD * SD);
    int rem = idx % (HD * SD);

    float p[CD];
    float mx = -1e30f;
#pragma unroll
    for (int c = 0; c < CD; c++) {
        p[c] = pooled[(size_t)(c * BD + b) * HD * SD + rem];
        mx = fmaxf(mx, p[c]);
    }
    float se = 0.f;
#pragma unroll
    for (int c = 0; c < CD; c++) {
        p[c] = __expf(p[c] - mx);
        se += p[c];
    }
    float inv = 1.f / se;
#pragma unroll
    for (int c = 0; c < CD; c++)
        wp[(size_t)(c * BD + b) * HD * SD + rem] = p[c] * inv;
}

// ---------------- launch ----------------
extern "C" void kernel_launch(void* const* d_in, const int* in_sizes, int n_in,
                              void* d_out, int out_size)
{
    const float* hidden = (const float*)d_in[0];
    const float* enc    = (const float*)d_in[1];
    const float* Wq     = (const float*)d_in[2];
    const float* Wk     = (const float*)d_in[3];
    const float* Wv     = (const float*)d_in[4];
    const float* Wo     = (const float*)d_in[5];
    const float* bo     = (const float*)d_in[6];
    float* out = (float*)d_out;

    float *pQ, *pA, *pK, *pV, *pPooled, *pWp;
    cudaGetSymbolAddress((void**)&pQ, g_Q);
    cudaGetSymbolAddress((void**)&pA, g_attn);
    cudaGetSymbolAddress((void**)&pK, g_K);
    cudaGetSymbolAddress((void**)&pV, g_V);
    cudaGetSymbolAddress((void**)&pPooled, g_pooled);
    cudaGetSymbolAddress((void**)&pWp, g_wp);

    // 1) Q = hidden @ Wq   [32768 x 1024 x 1024]
    {
        dim3 grid(DD / 128, (BCD * SD) / 128);
        tgemm_kernel<false><<<grid, 256>>>(hidden, Wq, pQ, BCD * SD, DD, DD,
                                           nullptr, nullptr, nullptr);
    }
    // 2) K = enc @ Wk, 3) V = enc @ Wv   [1280 x 1024 x 1024]
    {
        dim3 grid(DD / 128, (BCD * ED) / 128);
        tgemm_kernel<false><<<grid, 256>>>(enc, Wk, pK, BCD * ED, DD, DD,
                                           nullptr, nullptr, nullptr);
        tgemm_kernel<false><<<grid, 256>>>(enc, Wv, pV, BCD * ED, DD, DD,
                                           nullptr, nullptr, nullptr);
    }
    // 4) fused attention -> unscaled attn + pooled means
    {
        cudaFuncSetAttribute(attn_kernel, cudaFuncAttributeMaxDynamicSharedMemorySize,
                             ATTN_SMEM_BYTES);
        dim3 grid(SD / 64, HD, BCD);
        attn_kernel<<<grid, 256, ATTN_SMEM_BYTES>>>(pQ, pK, pV, pA, pPooled);
    }
    // 5) component-softmax weights
    {
        int n = BD * HD * SD;
        wp_kernel<<<(n + 255) / 256, 256>>>(pPooled, pWp);
    }
    // 6) out = (wp .* attn) @ Wo + bo + hidden   (wp folded into A-tile load)
    {
        dim3 grid(DD / 128, (BCD * SD) / 128);
        tgemm_kernel<true><<<grid, 256>>>(pA, Wo, out, BCD * SD, DD, DD,
                                          bo, hidden, pWp);
    }
}

// round 9
// speedup vs baseline: 1.4199x; 1.4199x over previous
#include <cuda_runtime.h>
#include <cuda_bf16.h>
#include <math.h>

#define BCD 8
#define SD  4096
#define DD  1024
#define ED  160
#define HD  16
#define DHD 64
#define CD  4
#define BD  2

// ---------------- scratch (static device globals; no allocation) ----------------
__device__ __nv_bfloat16 g_Qb[BCD * SD * DD];    // 64 MB
__device__ __nv_bfloat16 g_Kb[BCD * ED * DD];    // 2.5 MB
__device__ __nv_bfloat16 g_Vb[BCD * ED * DD];    // 2.5 MB
__device__ __nv_bfloat16 g_attnb[BCD * SD * DD]; // 64 MB (fits L2 for EPI GEMM re-reads)
__device__ float g_pooled[BCD * HD * SD];        // 2 MB
__device__ float g_wp[BCD * HD * SD];            // 2 MB

// ---------------- tf32 tensor-core GEMM: C = A[MxK] @ B[KxN] ------------------
// MODE 0: f32 A,   f32 out
// MODE 1: bf16 A * wp, f32 out + bias + resid
// MODE 2: f32 A,   bf16 out
#define TFPAD 136

__device__ __forceinline__ float tf32r(float x) {
    asm("cvt.rna.tf32.f32 %0, %1;" : "=f"(x) : "f"(x));
    return x;
}

__device__ __forceinline__ void mma_tf32(float* c, const float* a, const float* b) {
    asm volatile(
        "mma.sync.aligned.m16n8k8.row.col.f32.tf32.tf32.f32 "
        "{%0,%1,%2,%3}, {%4,%5,%6,%7}, {%8,%9}, {%0,%1,%2,%3};\n"
        : "+f"(c[0]), "+f"(c[1]), "+f"(c[2]), "+f"(c[3])
        : "r"(__float_as_uint(a[0])), "r"(__float_as_uint(a[1])),
          "r"(__float_as_uint(a[2])), "r"(__float_as_uint(a[3])),
          "r"(__float_as_uint(b[0])), "r"(__float_as_uint(b[1])));
}

__device__ __forceinline__ float wp_of(const float* __restrict__ wp, int row, int k) {
    int bc = row >> 12;
    int s  = row & 4095;
    int h  = k >> 6;
    return wp[((size_t)bc * HD + h) * SD + s];
}

template <int MODE>
__global__ __launch_bounds__(256)
void tgemm_kernel(const void* __restrict__ Av, const float* __restrict__ B,
                  void* __restrict__ Cv, int M, int N, int K,
                  const float* __restrict__ bias, const float* __restrict__ resid,
                  const float* __restrict__ wscale)
{
    __shared__ float As[2][16][TFPAD];
    __shared__ float Bs[2][16][TFPAD];

    const int tid  = threadIdx.x;
    const int lane = tid & 31;
    const int warp = tid >> 5;
    const int warp_m = warp & 3;
    const int warp_n = warp >> 2;
    const int bm = blockIdx.y * 128;
    const int bn = blockIdx.x * 128;

    const int arow = tid >> 2;
    const int acol = (tid & 3) * 4;
    const int brow = tid >> 5;
    const int bcol = (tid & 31) * 4;

    const float* Af = (const float*)Av;
    const __nv_bfloat16* Ab = (const __nv_bfloat16*)Av;

    float acc[2][8][4];
#pragma unroll
    for (int mi = 0; mi < 2; mi++)
#pragma unroll
        for (int ni = 0; ni < 8; ni++)
#pragma unroll
            for (int r = 0; r < 4; r++) acc[mi][ni][r] = 0.f;

    // ---- first tile into buffer 0 ----
#pragma unroll
    for (int i = 0; i < 2; i++) {
        int r = arow + i * 64;
        if (MODE == 1) {
            uint2 raw = *(const uint2*)&Ab[(size_t)(bm + r) * K + acol];
            float w = wp_of(wscale, bm + r, acol);
            __nv_bfloat162 p01 = *(__nv_bfloat162*)&raw.x;
            __nv_bfloat162 p23 = *(__nv_bfloat162*)&raw.y;
            As[0][acol + 0][r] = tf32r(__low2float(p01) * w);
            As[0][acol + 1][r] = tf32r(__high2float(p01) * w);
            As[0][acol + 2][r] = tf32r(__low2float(p23) * w);
            As[0][acol + 3][r] = tf32r(__high2float(p23) * w);
        } else {
            float4 a = *(const float4*)&Af[(size_t)(bm + r) * K + acol];
            As[0][acol + 0][r] = tf32r(a.x);
            As[0][acol + 1][r] = tf32r(a.y);
            As[0][acol + 2][r] = tf32r(a.z);
            As[0][acol + 3][r] = tf32r(a.w);
        }
    }
#pragma unroll
    for (int i = 0; i < 2; i++) {
        int r = brow + i * 8;
        float4 b = *(const float4*)&B[(size_t)r * N + bn + bcol];
        float4 t;
        t.x = tf32r(b.x); t.y = tf32r(b.y); t.z = tf32r(b.z); t.w = tf32r(b.w);
        *(float4*)&Bs[0][r][bcol] = t;
    }
    __syncthreads();

    int buf = 0;
    for (int k0 = 0; k0 < K; k0 += 16) {
        const bool more = (k0 + 16) < K;
        float4 pa[2];
        uint2  pab[2];
        float4 pb[2];
        float  pw[2];
        if (more) {
#pragma unroll
            for (int i = 0; i < 2; i++) {
                int r = arow + i * 64;
                if (MODE == 1) {
                    pab[i] = *(const uint2*)&Ab[(size_t)(bm + r) * K + k0 + 16 + acol];
                    pw[i]  = wp_of(wscale, bm + r, k0 + 16 + acol);
                } else {
                    pa[i] = *(const float4*)&Af[(size_t)(bm + r) * K + k0 + 16 + acol];
                }
            }
#pragma unroll
            for (int i = 0; i < 2; i++) {
                int r = brow + i * 8;
                pb[i] = *(const float4*)&B[(size_t)(k0 + 16 + r) * N + bn + bcol];
            }
        }

        // ---- compute on current buffer ----
#pragma unroll
        for (int kk = 0; kk < 2; kk++) {
            const int kA0 = kk * 8 + (lane & 3);
            const int kA1 = kA0 + 4;
            const int m0 = warp_m * 32 + (lane >> 2);
            const int n0 = warp_n * 64 + (lane >> 2);

            float a[2][4];
#pragma unroll
            for (int mi = 0; mi < 2; mi++) {
                int m = m0 + mi * 16;
                a[mi][0] = As[buf][kA0][m];
                a[mi][1] = As[buf][kA0][m + 8];
                a[mi][2] = As[buf][kA1][m];
                a[mi][3] = As[buf][kA1][m + 8];
            }
            float b[8][2];
#pragma unroll
            for (int ni = 0; ni < 8; ni++) {
                b[ni][0] = Bs[buf][kA0][n0 + ni * 8];
                b[ni][1] = Bs[buf][kA1][n0 + ni * 8];
            }
#pragma unroll
            for (int mi = 0; mi < 2; mi++)
#pragma unroll
                for (int ni = 0; ni < 8; ni++)
                    mma_tf32(acc[mi][ni], a[mi], b[ni]);
        }

        if (more) {
            int nb = buf ^ 1;
#pragma unroll
            for (int i = 0; i < 2; i++) {
                int r = arow + i * 64;
                if (MODE == 1) {
                    __nv_bfloat162 p01 = *(__nv_bfloat162*)&pab[i].x;
                    __nv_bfloat162 p23 = *(__nv_bfloat162*)&pab[i].y;
                    As[nb][acol + 0][r] = tf32r(__low2float(p01) * pw[i]);
                    As[nb][acol + 1][r] = tf32r(__high2float(p01) * pw[i]);
                    As[nb][acol + 2][r] = tf32r(__low2float(p23) * pw[i]);
                    As[nb][acol + 3][r] = tf32r(__high2float(p23) * pw[i]);
                } else {
                    As[nb][acol + 0][r] = tf32r(pa[i].x);
                    As[nb][acol + 1][r] = tf32r(pa[i].y);
                    As[nb][acol + 2][r] = tf32r(pa[i].z);
                    As[nb][acol + 3][r] = tf32r(pa[i].w);
                }
            }
#pragma unroll
            for (int i = 0; i < 2; i++) {
                int r = brow + i * 8;
                float4 t;
                t.x = tf32r(pb[i].x); t.y = tf32r(pb[i].y);
                t.z = tf32r(pb[i].z); t.w = tf32r(pb[i].w);
                *(float4*)&Bs[nb][r][bcol] = t;
            }
            __syncthreads();
            buf = nb;
        }
    }

    const int mrow = bm + warp_m * 32 + (lane >> 2);
    const int ncol = bn + warp_n * 64 + 2 * (lane & 3);
#pragma unroll
    for (int mi = 0; mi < 2; mi++) {
#pragma unroll
        for (int ni = 0; ni < 8; ni++) {
            int r0 = mrow + mi * 16;
            int c  = ncol + ni * 8;
            float2 v0 = make_float2(acc[mi][ni][0], acc[mi][ni][1]);
            float2 v1 = make_float2(acc[mi][ni][2], acc[mi][ni][3]);
            size_t i0 = (size_t)r0 * N + c;
            size_t i1 = (size_t)(r0 + 8) * N + c;
            if (MODE == 1) {
                float* C = (float*)Cv;
                float b0 = bias[c], b1 = bias[c + 1];
                const float2 r0v = *(const float2*)&resid[i0];
                const float2 r1v = *(const float2*)&resid[i1];
                v0.x += b0 + r0v.x; v0.y += b1 + r0v.y;
                v1.x += b0 + r1v.x; v1.y += b1 + r1v.y;
                *(float2*)&C[i0] = v0;
                *(float2*)&C[i1] = v1;
            } else if (MODE == 2) {
                __nv_bfloat16* C = (__nv_bfloat16*)Cv;
                *(__nv_bfloat162*)&C[i0] = __floats2bfloat162_rn(v0.x, v0.y);
                *(__nv_bfloat162*)&C[i1] = __floats2bfloat162_rn(v1.x, v1.y);
            } else {
                float* C = (float*)Cv;
                *(float2*)&C[i0] = v0;
                *(float2*)&C[i1] = v1;
            }
        }
    }
}

// ---------------- tensor-core attention -----------------------------------------
// grid (SD/128, HD, BCD), 256 thr = 8 warps; warp w owns rows [16w,16w+16).
// smem (bf16): union{ Qs[128][72] + Ks[160][72] | Ps[128][168] } then Vt[64][168]
#define QS_WST 36          // Qs/Ks row stride in 4B words (72 bf16)
#define PS_WST 84          // Ps/Vt row stride in 4B words (168 bf16)
#define KS_WOFF (128 * QS_WST)
#define VT_WOFF (128 * PS_WST)
#define AT2_SMEM_BYTES ((128 * PS_WST + 64 * PS_WST) * 4)   // 64512 B

__device__ __forceinline__ void mma_bf16(float* c, unsigned a0, unsigned a1,
                                         unsigned a2, unsigned a3,
                                         unsigned b0, unsigned b1) {
    asm volatile(
        "mma.sync.aligned.m16n8k16.row.col.f32.bf16.bf16.f32 "
        "{%0,%1,%2,%3}, {%4,%5,%6,%7}, {%8,%9}, {%0,%1,%2,%3};\n"
        : "+f"(c[0]), "+f"(c[1]), "+f"(c[2]), "+f"(c[3])
        : "r"(a0), "r"(a1), "r"(a2), "r"(a3), "r"(b0), "r"(b1));
}

__global__ __launch_bounds__(256)
void attn2_kernel(const __nv_bfloat16* __restrict__ Q,
                  const __nv_bfloat16* __restrict__ Kc,
                  const __nv_bfloat16* __restrict__ Vc,
                  __nv_bfloat16* __restrict__ Ou, float* __restrict__ pooled)
{
    extern __shared__ unsigned smw[];

    const int tid  = threadIdx.x;
    const int lane = tid & 31;
    const int warp = tid >> 5;
    const int g = lane >> 2;
    const int t = lane & 3;
    const int s0 = blockIdx.x * 128;
    const int h  = blockIdx.y;
    const int bc = blockIdx.z;

    // ---- load Q (128x64), K (160x64), V->Vt (64x160) ----
    {
        const unsigned* Qg = (const unsigned*)(Q + ((size_t)bc * SD + s0) * DD + h * DHD);
#pragma unroll
        for (int i = 0; i < 16; i++) {
            int idx = tid + 256 * i;
            int r = idx >> 5, c = idx & 31;
            smw[r * QS_WST + c] = Qg[(size_t)r * (DD / 2) + c];
        }
        const unsigned* Kg = (const unsigned*)(Kc + ((size_t)bc * ED) * DD + h * DHD);
#pragma unroll
        for (int i = 0; i < 20; i++) {
            int idx = tid + 256 * i;
            int r = idx >> 5, c = idx & 31;
            smw[KS_WOFF + r * QS_WST + c] = Kg[(size_t)r * (DD / 2) + c];
        }
        const unsigned* Vg = (const unsigned*)(Vc + ((size_t)bc * ED) * DD + h * DHD);
        __nv_bfloat16* Vt = (__nv_bfloat16*)(smw + VT_WOFF);
#pragma unroll
        for (int i = 0; i < 20; i++) {
            int idx = tid + 256 * i;
            int e = idx >> 5, d2 = idx & 31;
            unsigned w = Vg[(size_t)e * (DD / 2) + d2];
            __nv_bfloat162 v2 = *(__nv_bfloat162*)&w;
            Vt[(2 * d2) * (2 * PS_WST) + e]     = v2.x;
            Vt[(2 * d2 + 1) * (2 * PS_WST) + e] = v2.y;
        }
    }
    __syncthreads();

    // ---- scores: [16 x 160] per warp ----
    float sc[20][4];
#pragma unroll
    for (int nt = 0; nt < 20; nt++)
#pragma unroll
        for (int j = 0; j < 4; j++) sc[nt][j] = 0.f;

    const int ra = (16 * warp + g) * QS_WST;
    const int rb = (16 * warp + g + 8) * QS_WST;
#pragma unroll
    for (int kk = 0; kk < 4; kk++) {
        unsigned a0 = smw[ra + 8 * kk + t];
        unsigned a1 = smw[rb + 8 * kk + t];
        unsigned a2 = smw[ra + 8 * kk + t + 4];
        unsigned a3 = smw[rb + 8 * kk + t + 4];
#pragma unroll
        for (int nt = 0; nt < 20; nt++) {
            int kb = KS_WOFF + (8 * nt + g) * QS_WST + 8 * kk + t;
            mma_bf16(sc[nt], a0, a1, a2, a3, smw[kb], smw[kb + 4]);
        }
    }

    // ---- softmax + pooled ----
    const float SCALE = 0.125f;
    float m0 = -1e30f, m1 = -1e30f, t0 = 0.f, t1 = 0.f;
#pragma unroll
    for (int nt = 0; nt < 20; nt++) {
        sc[nt][0] *= SCALE; sc[nt][1] *= SCALE;
        sc[nt][2] *= SCALE; sc[nt][3] *= SCALE;
        t0 += sc[nt][0] + sc[nt][1];
        t1 += sc[nt][2] + sc[nt][3];
        m0 = fmaxf(m0, fmaxf(sc[nt][0], sc[nt][1]));
        m1 = fmaxf(m1, fmaxf(sc[nt][2], sc[nt][3]));
    }
#pragma unroll
    for (int off = 1; off <= 2; off <<= 1) {
        m0 = fmaxf(m0, __shfl_xor_sync(0xffffffffu, m0, off));
        m1 = fmaxf(m1, __shfl_xor_sync(0xffffffffu, m1, off));
        t0 += __shfl_xor_sync(0xffffffffu, t0, off);
        t1 += __shfl_xor_sync(0xffffffffu, t1, off);
    }
    if (t == 0) {
        size_t pb = ((size_t)bc * HD + h) * SD + s0 + 16 * warp;
        pooled[pb + g]     = t0 * (1.f / 160.f);
        pooled[pb + g + 8] = t1 * (1.f / 160.f);
    }
    float e0 = 0.f, e1 = 0.f;
#pragma unroll
    for (int nt = 0; nt < 20; nt++) {
        sc[nt][0] = __expf(sc[nt][0] - m0); e0 += sc[nt][0];
        sc[nt][1] = __expf(sc[nt][1] - m0); e0 += sc[nt][1];
        sc[nt][2] = __expf(sc[nt][2] - m1); e1 += sc[nt][2];
        sc[nt][3] = __expf(sc[nt][3] - m1); e1 += sc[nt][3];
    }
#pragma unroll
    for (int off = 1; off <= 2; off <<= 1) {
        e0 += __shfl_xor_sync(0xffffffffu, e0, off);
        e1 += __shfl_xor_sync(0xffffffffu, e1, off);
    }
    const float i0 = 1.f / e0, i1 = 1.f / e1;

    __syncthreads();   // all warps done reading Qs/Ks before Ps overwrites them

    // ---- write P (bf16) to smem ----
    const int pr0 = (16 * warp + g) * PS_WST;
    const int pr1 = (16 * warp + g + 8) * PS_WST;
#pragma unroll
    for (int nt = 0; nt < 20; nt++) {
        __nv_bfloat162 p0 = __floats2bfloat162_rn(sc[nt][0] * i0, sc[nt][1] * i0);
        __nv_bfloat162 p1 = __floats2bfloat162_rn(sc[nt][2] * i1, sc[nt][3] * i1);
        smw[pr0 + 4 * nt + t] = *(unsigned*)&p0;
        smw[pr1 + 4 * nt + t] = *(unsigned*)&p1;
    }
    __syncwarp();

    // ---- PV: out[16 x 64] per warp ----
    float o[8][4];
#pragma unroll
    for (int nt = 0; nt < 8; nt++)
#pragma unroll
        for (int j = 0; j < 4; j++) o[nt][j] = 0.f;

#pragma unroll
    for (int kk = 0; kk < 10; kk++) {
        unsigned a0 = smw[pr0 + 8 * kk + t];
        unsigned a1 = smw[pr1 + 8 * kk + t];
        unsigned a2 = smw[pr0 + 8 * kk + t + 4];
        unsigned a3 = smw[pr1 + 8 * kk + t + 4];
#pragma unroll
        for (int nt = 0; nt < 8; nt++) {
            int vb = VT_WOFF + (8 * nt + g) * PS_WST + 8 * kk + t;
            mma_bf16(o[nt], a0, a1, a2, a3, smw[vb], smw[vb + 4]);
        }
    }

    // ---- store out (bf16) ----
    const size_t ob0 = ((size_t)bc * SD + s0 + 16 * warp + g) * DD + h * DHD;
    const size_t ob1 = ob0 + 8 * DD;
#pragma unroll
    for (int nt = 0; nt < 8; nt++) {
        int c = 8 * nt + 2 * t;
        *(__nv_bfloat162*)&Ou[ob0 + c] = __floats2bfloat162_rn(o[nt][0], o[nt][1]);
        *(__nv_bfloat162*)&Ou[ob1 + c] = __floats2bfloat162_rn(o[nt][2], o[nt][3]);
    }
}

// ---------------- component softmax over pooled -> wp ----------------
__global__ void wp_kernel(const float* __restrict__ pooled, float* __restrict__ wp)
{
    int idx = blockIdx.x * blockDim.x + threadIdx.x;
    if (idx >= BD * HD * SD) return;
    int b = idx / (HD * SD);
    int rem = idx % (HD * SD);

    float p[CD];
    float mx = -1e30f;
#pragma unroll
    for (int c = 0; c < CD; c++) {
        p[c] = pooled[(size_t)(c * BD + b) * HD * SD + rem];
        mx = fmaxf(mx, p[c]);
    }
    float se = 0.f;
#pragma unroll
    for (int c = 0; c < CD; c++) {
        p[c] = __expf(p[c] - mx);
        se += p[c];
    }
    float inv = 1.f / se;
#pragma unroll
    for (int c = 0; c < CD; c++)
        wp[(size_t)(c * BD + b) * HD * SD + rem] = p[c] * inv;
}

// ---------------- launch ----------------
extern "C" void kernel_launch(void* const* d_in, const int* in_sizes, int n_in,
                              void* d_out, int out_size)
{
    const float* hidden = (const float*)d_in[0];
    const float* enc    = (const float*)d_in[1];
    const float* Wq     = (const float*)d_in[2];
    const float* Wk     = (const float*)d_in[3];
    const float* Wv     = (const float*)d_in[4];
    const float* Wo     = (const float*)d_in[5];
    const float* bo     = (const float*)d_in[6];
    float* out = (float*)d_out;

    __nv_bfloat16 *pQ, *pK, *pV, *pA;
    float *pPooled, *pWp;
    cudaGetSymbolAddress((void**)&pQ, g_Qb);
    cudaGetSymbolAddress((void**)&pK, g_Kb);
    cudaGetSymbolAddress((void**)&pV, g_Vb);
    cudaGetSymbolAddress((void**)&pA, g_attnb);
    cudaGetSymbolAddress((void**)&pPooled, g_pooled);
    cudaGetSymbolAddress((void**)&pWp, g_wp);

    // 1) Q = hidden @ Wq -> bf16   [32768 x 1024 x 1024]
    {
        dim3 grid(DD / 128, (BCD * SD) / 128);
        tgemm_kernel<2><<<grid, 256>>>(hidden, Wq, pQ, BCD * SD, DD, DD,
                                       nullptr, nullptr, nullptr);
    }
    // 2) K, V = enc @ {Wk, Wv} -> bf16   [1280 x 1024 x 1024]
    {
        dim3 grid(DD / 128, (BCD * ED) / 128);
        tgemm_kernel<2><<<grid, 256>>>(enc, Wk, pK, BCD * ED, DD, DD,
                                       nullptr, nullptr, nullptr);
        tgemm_kernel<2><<<grid, 256>>>(enc, Wv, pV, BCD * ED, DD, DD,
                                       nullptr, nullptr, nullptr);
    }
    // 4) tensor-core attention -> unscaled attn (bf16) + pooled
    {
        cudaFuncSetAttribute(attn2_kernel, cudaFuncAttributeMaxDynamicSharedMemorySize,
                             AT2_SMEM_BYTES);
        dim3 grid(SD / 128, HD, BCD);
        attn2_kernel<<<grid, 256, AT2_SMEM_BYTES>>>(pQ, pK, pV, pA, pPooled);
    }
    // 5) component-softmax weights
    {
        int n = BD * HD * SD;
        wp_kernel<<<(n + 255) / 256, 256>>>(pPooled, pWp);
    }
    // 6) out = (wp .* attn_bf16) @ Wo + bo + hidden
    {
        dim3 grid(DD / 128, (BCD * SD) / 128);
        tgemm_kernel<1><<<grid, 256>>>(pA, Wo, out, BCD * SD, DD, DD,
                                       bo, hidden, pWp);
    }
}

// round 10
// speedup vs baseline: 1.6652x; 1.1727x over previous
#include <cuda_runtime.h>
#include <cuda_bf16.h>
#include <math.h>

#define BCD 8
#define SD  4096
#define DD  1024
#define ED  160
#define HD  16
#define DHD 64
#define CD  4
#define BD  2

// ---------------- scratch (static device globals; no allocation) ----------------
__device__ __nv_bfloat16 g_hb[BCD * SD * DD];    // 64 MB  hidden bf16
__device__ __nv_bfloat16 g_eb[BCD * ED * DD];    // 2.5 MB enc bf16
__device__ __nv_bfloat16 g_Wqt[DD * DD];         // 2 MB   Wq^T bf16 [N][K]
__device__ __nv_bfloat16 g_Wkt[DD * DD];
__device__ __nv_bfloat16 g_Wvt[DD * DD];
__device__ __nv_bfloat16 g_Wot[DD * DD];
__device__ __nv_bfloat16 g_Qb[BCD * SD * DD];    // 64 MB
__device__ __nv_bfloat16 g_Kb[BCD * ED * DD];
__device__ __nv_bfloat16 g_Vb[BCD * ED * DD];
__device__ __nv_bfloat16 g_attnb[BCD * SD * DD]; // 64 MB
__device__ float g_pooled[BCD * HD * SD];
__device__ float g_wp[BCD * HD * SD];

__device__ __forceinline__ void mma_bf16(float* c, unsigned a0, unsigned a1,
                                         unsigned a2, unsigned a3,
                                         unsigned b0, unsigned b1) {
    asm volatile(
        "mma.sync.aligned.m16n8k16.row.col.f32.bf16.bf16.f32 "
        "{%0,%1,%2,%3}, {%4,%5,%6,%7}, {%8,%9}, {%0,%1,%2,%3};\n"
        : "+f"(c[0]), "+f"(c[1]), "+f"(c[2]), "+f"(c[3])
        : "r"(a0), "r"(a1), "r"(a2), "r"(a3), "r"(b0), "r"(b1));
}

// ---------------- f32 -> bf16 flat convert ----------------
__global__ void cvt_kernel(const float* __restrict__ in, __nv_bfloat16* __restrict__ out,
                           int n4)
{
    int i = blockIdx.x * blockDim.x + threadIdx.x;
    if (i >= n4) return;
    float4 v = *(const float4*)&in[(size_t)i * 4];
    unsigned w0, w1;
    __nv_bfloat162 p0 = __floats2bfloat162_rn(v.x, v.y);
    __nv_bfloat162 p1 = __floats2bfloat162_rn(v.z, v.w);
    w0 = *(unsigned*)&p0; w1 = *(unsigned*)&p1;
    uint2 o = make_uint2(w0, w1);
    *(uint2*)&out[(size_t)i * 4] = o;
}

// ---------------- weight transpose+convert: in f32[K=1024][N=1024] -> out bf16[N][K]
__global__ void transpose_cvt_kernel(const float* __restrict__ in,
                                     __nv_bfloat16* __restrict__ out)
{
    __shared__ float tile[32][33];
    int x = blockIdx.x * 32 + threadIdx.x;   // n
    int y0 = blockIdx.y * 32;                // k base
#pragma unroll
    for (int j = 0; j < 32; j += 8)
        tile[threadIdx.y + j][threadIdx.x] = in[(size_t)(y0 + threadIdx.y + j) * DD + x];
    __syncthreads();
    int xo = blockIdx.y * 32 + threadIdx.x;  // k
    int yo = blockIdx.x * 32;                // n base
#pragma unroll
    for (int j = 0; j < 32; j += 8)
        out[(size_t)(yo + threadIdx.y + j) * DD + xo] =
            __float2bfloat16(tile[threadIdx.x][threadIdx.y + j]);
}

// ---------------- bf16 tensor-core GEMM: C = A[MxK] @ Bt^T (Bt = [N][K] bf16) ----
// MODE 0: C bf16;  MODE 1: A scaled by wp, C f32 + bias + resid
// CTA 128x128, K-stage 32, 8 warps (4 M x 2 N), warp tile 32x64, m16n8k16.
#define AW 20   // smem row stride in 4B words (16 data + 4 pad) — conflict-free

template <int MODE>
__global__ __launch_bounds__(256)
void bgemm_kernel(const __nv_bfloat16* __restrict__ A,
                  const __nv_bfloat16* __restrict__ Bt,
                  void* __restrict__ Cv, int M, int N, int K,
                  const float* __restrict__ bias, const float* __restrict__ resid,
                  const float* __restrict__ wp)
{
    __shared__ unsigned As[2][128 * AW];
    __shared__ unsigned Bs[2][128 * AW];

    const int tid  = threadIdx.x;
    const int lane = tid & 31;
    const int warp = tid >> 5;
    const int g = lane >> 2;
    const int t = lane & 3;
    const int warp_m = warp & 3;
    const int warp_n = warp >> 2;
    const int bm = blockIdx.y * 128;
    const int bn = blockIdx.x * 128;
    const int K2 = K >> 1;   // words per row

    const unsigned* Ag = (const unsigned*)A;
    const unsigned* Bg = (const unsigned*)Bt;

    float acc[2][8][4];
#pragma unroll
    for (int mi = 0; mi < 2; mi++)
#pragma unroll
        for (int nt = 0; nt < 8; nt++)
#pragma unroll
            for (int j = 0; j < 4; j++) acc[mi][nt][j] = 0.f;

    // ---- copy helpers inline: stage k0 -> buffer b ----
    // indexing: idx = tid + 256*i, r = idx>>4 (row 0..127), c = idx&15 (word)
#define LOAD_STAGE(b, k0)                                                        \
    {                                                                            \
        int kw = (k0) >> 1;                                                      \
        _Pragma("unroll")                                                        \
        for (int i = 0; i < 8; i++) {                                            \
            int idx = tid + 256 * i;                                             \
            int r = idx >> 4, c = idx & 15;                                      \
            unsigned aw = Ag[(size_t)(bm + r) * K2 + kw + c];                    \
            if (MODE == 1) {                                                     \
                int row = bm + r;                                                \
                int bc = row >> 12, s = row & 4095, hh = (k0) >> 6;              \
                float w = wp[((size_t)bc * HD + hh) * SD + s];                   \
                float2 f = __bfloat1622float2(*(__nv_bfloat162*)&aw);            \
                __nv_bfloat162 p = __floats2bfloat162_rn(f.x * w, f.y * w);      \
                aw = *(unsigned*)&p;                                             \
            }                                                                    \
            As[b][r * AW + c] = aw;                                              \
            Bs[b][r * AW + c] = Bg[(size_t)(bn + r) * K2 + kw + c];              \
        }                                                                        \
    }

    LOAD_STAGE(0, 0)
    __syncthreads();

    int buf = 0;
    for (int k0 = 0; k0 < K; k0 += 32) {
        const bool more = (k0 + 32) < K;
        // prefetch next stage into regs
        unsigned pa[8], pb[8];
        float pwv[8];
        if (more) {
            int kw = (k0 + 32) >> 1;
#pragma unroll
            for (int i = 0; i < 8; i++) {
                int idx = tid + 256 * i;
                int r = idx >> 4, c = idx & 15;
                pa[i] = Ag[(size_t)(bm + r) * K2 + kw + c];
                pb[i] = Bg[(size_t)(bn + r) * K2 + kw + c];
                if (MODE == 1) {
                    int row = bm + r;
                    int bc = row >> 12, s = row & 4095, hh = (k0 + 32) >> 6;
                    pwv[i] = wp[((size_t)bc * HD + hh) * SD + s];
                }
            }
        }

        // compute: 2 x k16 steps
#pragma unroll
        for (int s16 = 0; s16 < 2; s16++) {
            const int off = 8 * s16;
            unsigned a0[2], a1[2], a2[2], a3[2];
#pragma unroll
            for (int mi = 0; mi < 2; mi++) {
                int ra = (warp_m * 32 + 16 * mi + g) * AW + off + t;
                a0[mi] = As[buf][ra];
                a1[mi] = As[buf][ra + 8 * AW];
                a2[mi] = As[buf][ra + 4];
                a3[mi] = As[buf][ra + 8 * AW + 4];
            }
#pragma unroll
            for (int nt = 0; nt < 8; nt++) {
                int rb = (warp_n * 64 + 8 * nt + g) * AW + off + t;
                unsigned b0 = Bs[buf][rb];
                unsigned b1 = Bs[buf][rb + 4];
#pragma unroll
                for (int mi = 0; mi < 2; mi++)
                    mma_bf16(acc[mi][nt], a0[mi], a1[mi], a2[mi], a3[mi], b0, b1);
            }
        }

        if (more) {
            int nb = buf ^ 1;
#pragma unroll
            for (int i = 0; i < 8; i++) {
                int idx = tid + 256 * i;
                int r = idx >> 4, c = idx & 15;
                unsigned aw = pa[i];
                if (MODE == 1) {
                    float2 f = __bfloat1622float2(*(__nv_bfloat162*)&aw);
                    __nv_bfloat162 p = __floats2bfloat162_rn(f.x * pwv[i], f.y * pwv[i]);
                    aw = *(unsigned*)&p;
                }
                As[nb][r * AW + c] = aw;
                Bs[nb][r * AW + c] = pb[i];
            }
            __syncthreads();
            buf = nb;
        }
    }

    // ---- epilogue ----
#pragma unroll
    for (int mi = 0; mi < 2; mi++) {
        int r0 = bm + warp_m * 32 + 16 * mi + g;
#pragma unroll
        for (int nt = 0; nt < 8; nt++) {
            int c = bn + warp_n * 64 + 8 * nt + 2 * t;
            size_t i0 = (size_t)r0 * N + c;
            size_t i1 = (size_t)(r0 + 8) * N + c;
            if (MODE == 1) {
                float* C = (float*)Cv;
                float b0 = bias[c], b1 = bias[c + 1];
                const float2 r0v = *(const float2*)&resid[i0];
                const float2 r1v = *(const float2*)&resid[i1];
                *(float2*)&C[i0] = make_float2(acc[mi][nt][0] + b0 + r0v.x,
                                               acc[mi][nt][1] + b1 + r0v.y);
                *(float2*)&C[i1] = make_float2(acc[mi][nt][2] + b0 + r1v.x,
                                               acc[mi][nt][3] + b1 + r1v.y);
            } else {
                __nv_bfloat16* C = (__nv_bfloat16*)Cv;
                *(__nv_bfloat162*)&C[i0] = __floats2bfloat162_rn(acc[mi][nt][0], acc[mi][nt][1]);
                *(__nv_bfloat162*)&C[i1] = __floats2bfloat162_rn(acc[mi][nt][2], acc[mi][nt][3]);
            }
        }
    }
}

// ---------------- tensor-core attention (unchanged from R9 PASS) ----------------
#define QS_WST 36
#define PS_WST 84
#define KS_WOFF (128 * QS_WST)
#define VT_WOFF (128 * PS_WST)
#define AT2_SMEM_BYTES ((128 * PS_WST + 64 * PS_WST) * 4)

__global__ __launch_bounds__(256)
void attn2_kernel(const __nv_bfloat16* __restrict__ Q,
                  const __nv_bfloat16* __restrict__ Kc,
                  const __nv_bfloat16* __restrict__ Vc,
                  __nv_bfloat16* __restrict__ Ou, float* __restrict__ pooled)
{
    extern __shared__ unsigned smw[];

    const int tid  = threadIdx.x;
    const int lane = tid & 31;
    const int warp = tid >> 5;
    const int g = lane >> 2;
    const int t = lane & 3;
    const int s0 = blockIdx.x * 128;
    const int h  = blockIdx.y;
    const int bc = blockIdx.z;

    {
        const unsigned* Qg = (const unsigned*)(Q + ((size_t)bc * SD + s0) * DD + h * DHD);
#pragma unroll
        for (int i = 0; i < 16; i++) {
            int idx = tid + 256 * i;
            int r = idx >> 5, c = idx & 31;
            smw[r * QS_WST + c] = Qg[(size_t)r * (DD / 2) + c];
        }
        const unsigned* Kg = (const unsigned*)(Kc + ((size_t)bc * ED) * DD + h * DHD);
#pragma unroll
        for (int i = 0; i < 20; i++) {
            int idx = tid + 256 * i;
            int r = idx >> 5, c = idx & 31;
            smw[KS_WOFF + r * QS_WST + c] = Kg[(size_t)r * (DD / 2) + c];
        }
        const unsigned* Vg = (const unsigned*)(Vc + ((size_t)bc * ED) * DD + h * DHD);
        __nv_bfloat16* Vt = (__nv_bfloat16*)(smw + VT_WOFF);
#pragma unroll
        for (int i = 0; i < 20; i++) {
            int idx = tid + 256 * i;
            int e = idx >> 5, d2 = idx & 31;
            unsigned w = Vg[(size_t)e * (DD / 2) + d2];
            __nv_bfloat162 v2 = *(__nv_bfloat162*)&w;
            Vt[(2 * d2) * (2 * PS_WST) + e]     = v2.x;
            Vt[(2 * d2 + 1) * (2 * PS_WST) + e] = v2.y;
        }
    }
    __syncthreads();

    float sc[20][4];
#pragma unroll
    for (int nt = 0; nt < 20; nt++)
#pragma unroll
        for (int j = 0; j < 4; j++) sc[nt][j] = 0.f;

    const int ra = (16 * warp + g) * QS_WST;
    const int rb = (16 * warp + g + 8) * QS_WST;
#pragma unroll
    for (int kk = 0; kk < 4; kk++) {
        unsigned a0 = smw[ra + 8 * kk + t];
        unsigned a1 = smw[rb + 8 * kk + t];
        unsigned a2 = smw[ra + 8 * kk + t + 4];
        unsigned a3 = smw[rb + 8 * kk + t + 4];
#pragma unroll
        for (int nt = 0; nt < 20; nt++) {
            int kb = KS_WOFF + (8 * nt + g) * QS_WST + 8 * kk + t;
            mma_bf16(sc[nt], a0, a1, a2, a3, smw[kb], smw[kb + 4]);
        }
    }

    const float SCALE = 0.125f;
    float m0 = -1e30f, m1 = -1e30f, t0 = 0.f, t1 = 0.f;
#pragma unroll
    for (int nt = 0; nt < 20; nt++) {
        sc[nt][0] *= SCALE; sc[nt][1] *= SCALE;
        sc[nt][2] *= SCALE; sc[nt][3] *= SCALE;
        t0 += sc[nt][0] + sc[nt][1];
        t1 += sc[nt][2] + sc[nt][3];
        m0 = fmaxf(m0, fmaxf(sc[nt][0], sc[nt][1]));
        m1 = fmaxf(m1, fmaxf(sc[nt][2], sc[nt][3]));
    }
#pragma unroll
    for (int off = 1; off <= 2; off <<= 1) {
        m0 = fmaxf(m0, __shfl_xor_sync(0xffffffffu, m0, off));
        m1 = fmaxf(m1, __shfl_xor_sync(0xffffffffu, m1, off));
        t0 += __shfl_xor_sync(0xffffffffu, t0, off);
        t1 += __shfl_xor_sync(0xffffffffu, t1, off);
    }
    if (t == 0) {
        size_t pb = ((size_t)bc * HD + h) * SD + s0 + 16 * warp;
        pooled[pb + g]     = t0 * (1.f / 160.f);
        pooled[pb + g + 8] = t1 * (1.f / 160.f);
    }
    float e0 = 0.f, e1 = 0.f;
#pragma unroll
    for (int nt = 0; nt < 20; nt++) {
        sc[nt][0] = __expf(sc[nt][0] - m0); e0 += sc[nt][0];
        sc[nt][1] = __expf(sc[nt][1] - m0); e0 += sc[nt][1];
        sc[nt][2] = __expf(sc[nt][2] - m1); e1 += sc[nt][2];
        sc[nt][3] = __expf(sc[nt][3] - m1); e1 += sc[nt][3];
    }
#pragma unroll
    for (int off = 1; off <= 2; off <<= 1) {
        e0 += __shfl_xor_sync(0xffffffffu, e0, off);
        e1 += __shfl_xor_sync(0xffffffffu, e1, off);
    }
    const float i0 = 1.f / e0, i1 = 1.f / e1;

    __syncthreads();

    const int pr0 = (16 * warp + g) * PS_WST;
    const int pr1 = (16 * warp + g + 8) * PS_WST;
#pragma unroll
    for (int nt = 0; nt < 20; nt++) {
        __nv_bfloat162 p0 = __floats2bfloat162_rn(sc[nt][0] * i0, sc[nt][1] * i0);
        __nv_bfloat162 p1 = __floats2bfloat162_rn(sc[nt][2] * i1, sc[nt][3] * i1);
        smw[pr0 + 4 * nt + t] = *(unsigned*)&p0;
        smw[pr1 + 4 * nt + t] = *(unsigned*)&p1;
    }
    __syncwarp();

    float o[8][4];
#pragma unroll
    for (int nt = 0; nt < 8; nt++)
#pragma unroll
        for (int j = 0; j < 4; j++) o[nt][j] = 0.f;

#pragma unroll
    for (int kk = 0; kk < 10; kk++) {
        unsigned a0 = smw[pr0 + 8 * kk + t];
        unsigned a1 = smw[pr1 + 8 * kk + t];
        unsigned a2 = smw[pr0 + 8 * kk + t + 4];
        unsigned a3 = smw[pr1 + 8 * kk + t + 4];
#pragma unroll
        for (int nt = 0; nt < 8; nt++) {
            int vb = VT_WOFF + (8 * nt + g) * PS_WST + 8 * kk + t;
            mma_bf16(o[nt], a0, a1, a2, a3, smw[vb], smw[vb + 4]);
        }
    }

    const size_t ob0 = ((size_t)bc * SD + s0 + 16 * warp + g) * DD + h * DHD;
    const size_t ob1 = ob0 + 8 * DD;
#pragma unroll
    for (int nt = 0; nt < 8; nt++) {
        int c = 8 * nt + 2 * t;
        *(__nv_bfloat162*)&Ou[ob0 + c] = __floats2bfloat162_rn(o[nt][0], o[nt][1]);
        *(__nv_bfloat162*)&Ou[ob1 + c] = __floats2bfloat162_rn(o[nt][2], o[nt][3]);
    }
}

// ---------------- component softmax over pooled -> wp ----------------
__global__ void wp_kernel(const float* __restrict__ pooled, float* __restrict__ wp)
{
    int idx = blockIdx.x * blockDim.x + threadIdx.x;
    if (idx >= BD * HD * SD) return;
    int b = idx / (HD * SD);
    int rem = idx % (HD * SD);

    float p[CD];
    float mx = -1e30f;
#pragma unroll
    for (int c = 0; c < CD; c++) {
        p[c] = pooled[(size_t)(c * BD + b) * HD * SD + rem];
        mx = fmaxf(mx, p[c]);
    }
    float se = 0.f;
#pragma unroll
    for (int c = 0; c < CD; c++) {
        p[c] = __expf(p[c] - mx);
        se += p[c];
    }
    float inv = 1.f / se;
#pragma unroll
    for (int c = 0; c < CD; c++)
        wp[(size_t)(c * BD + b) * HD * SD + rem] = p[c] * inv;
}

// ---------------- launch ----------------
extern "C" void kernel_launch(void* const* d_in, const int* in_sizes, int n_in,
                              void* d_out, int out_size)
{
    const float* hidden = (const float*)d_in[0];
    const float* enc    = (const float*)d_in[1];
    const float* Wq     = (const float*)d_in[2];
    const float* Wk     = (const float*)d_in[3];
    const float* Wv     = (const float*)d_in[4];
    const float* Wo     = (const float*)d_in[5];
    const float* bo     = (const float*)d_in[6];
    float* out = (float*)d_out;

    __nv_bfloat16 *pHb, *pEb, *pWqt, *pWkt, *pWvt, *pWot, *pQ, *pK, *pV, *pA;
    float *pPooled, *pWp;
    cudaGetSymbolAddress((void**)&pHb, g_hb);
    cudaGetSymbolAddress((void**)&pEb, g_eb);
    cudaGetSymbolAddress((void**)&pWqt, g_Wqt);
    cudaGetSymbolAddress((void**)&pWkt, g_Wkt);
    cudaGetSymbolAddress((void**)&pWvt, g_Wvt);
    cudaGetSymbolAddress((void**)&pWot, g_Wot);
    cudaGetSymbolAddress((void**)&pQ, g_Qb);
    cudaGetSymbolAddress((void**)&pK, g_Kb);
    cudaGetSymbolAddress((void**)&pV, g_Vb);
    cudaGetSymbolAddress((void**)&pA, g_attnb);
    cudaGetSymbolAddress((void**)&pPooled, g_pooled);
    cudaGetSymbolAddress((void**)&pWp, g_wp);

    // 0) pre-convert activations, pre-transpose weights
    {
        int n4h = BCD * SD * DD / 4;
        cvt_kernel<<<(n4h + 255) / 256, 256>>>(hidden, pHb, n4h);
        int n4e = BCD * ED * DD / 4;
        cvt_kernel<<<(n4e + 255) / 256, 256>>>(enc, pEb, n4e);
        dim3 tg(DD / 32, DD / 32), tb(32, 8);
        transpose_cvt_kernel<<<tg, tb>>>(Wq, pWqt);
        transpose_cvt_kernel<<<tg, tb>>>(Wk, pWkt);
        transpose_cvt_kernel<<<tg, tb>>>(Wv, pWvt);
        transpose_cvt_kernel<<<tg, tb>>>(Wo, pWot);
    }
    // 1) Q = hidden @ Wq -> bf16
    {
        dim3 grid(DD / 128, (BCD * SD) / 128);
        bgemm_kernel<0><<<grid, 256>>>(pHb, pWqt, pQ, BCD * SD, DD, DD,
                                       nullptr, nullptr, nullptr);
    }
    // 2) K, V = enc @ {Wk, Wv} -> bf16
    {
        dim3 grid(DD / 128, (BCD * ED) / 128);
        bgemm_kernel<0><<<grid, 256>>>(pEb, pWkt, pK, BCD * ED, DD, DD,
                                       nullptr, nullptr, nullptr);
        bgemm_kernel<0><<<grid, 256>>>(pEb, pWvt, pV, BCD * ED, DD, DD,
                                       nullptr, nullptr, nullptr);
    }
    // 3) tensor-core attention -> unscaled attn (bf16) + pooled
    {
        cudaFuncSetAttribute(attn2_kernel, cudaFuncAttributeMaxDynamicSharedMemorySize,
                             AT2_SMEM_BYTES);
        dim3 grid(SD / 128, HD, BCD);
        attn2_kernel<<<grid, 256, AT2_SMEM_BYTES>>>(pQ, pK, pV, pA, pPooled);
    }
    // 4) component-softmax weights
    {
        int n = BD * HD * SD;
        wp_kernel<<<(n + 255) / 256, 256>>>(pPooled, pWp);
    }
    // 5) out = (wp .* attn) @ Wo + bo + hidden
    {
        dim3 grid(DD / 128, (BCD * SD) / 128);
        bgemm_kernel<1><<<grid, 256>>>(pA, pWot, out, BCD * SD, DD, DD,
                                       bo, hidden, pWp);
    }
}

// round 16
// speedup vs baseline: 2.0544x; 1.2338x over previous
#include <cuda_runtime.h>
#include <cuda_bf16.h>
#include <math.h>

#define BCD 8
#define SD  4096
#define DD  1024
#define ED  160
#define HD  16
#define DHD 64
#define CD  4
#define BD  2

// ---------------- scratch (static device globals; no allocation) ----------------
__device__ __nv_bfloat16 g_hb[BCD * SD * DD];    // 64 MB  hidden bf16
__device__ __nv_bfloat16 g_eb[BCD * ED * DD];    // 2.5 MB enc bf16
__device__ __nv_bfloat16 g_Wqt[DD * DD];         // 2 MB   Wq^T bf16 [N][K]
__device__ __nv_bfloat16 g_Wkt[DD * DD];
__device__ __nv_bfloat16 g_Wvt[DD * DD];
__device__ __nv_bfloat16 g_Wot[DD * DD];
__device__ __nv_bfloat16 g_Qb[BCD * SD * DD];    // 64 MB
__device__ __nv_bfloat16 g_Kb[BCD * ED * DD];
__device__ __nv_bfloat16 g_Vb[BCD * ED * DD];
__device__ __nv_bfloat16 g_attnb[BCD * SD * DD]; // 64 MB
__device__ float g_pooled[BCD * HD * SD];
__device__ float g_wp[BCD * HD * SD];

__device__ __forceinline__ void mma_bf16(float* c, unsigned a0, unsigned a1,
                                         unsigned a2, unsigned a3,
                                         unsigned b0, unsigned b1) {
    asm volatile(
        "mma.sync.aligned.m16n8k16.row.col.f32.bf16.bf16.f32 "
        "{%0,%1,%2,%3}, {%4,%5,%6,%7}, {%8,%9}, {%0,%1,%2,%3};\n"
        : "+f"(c[0]), "+f"(c[1]), "+f"(c[2]), "+f"(c[3])
        : "r"(a0), "r"(a1), "r"(a2), "r"(a3), "r"(b0), "r"(b1));
}

__device__ __forceinline__ void ldsm4(unsigned& r0, unsigned& r1, unsigned& r2,
                                      unsigned& r3, const void* p) {
    unsigned addr = (unsigned)__cvta_generic_to_shared(p);
    asm volatile("ldmatrix.sync.aligned.m8n8.x4.shared.b16 {%0,%1,%2,%3}, [%4];"
                 : "=r"(r0), "=r"(r1), "=r"(r2), "=r"(r3) : "r"(addr));
}

// ---------------- f32 -> bf16 flat convert ----------------
__global__ void cvt_kernel(const float* __restrict__ in, __nv_bfloat16* __restrict__ out,
                           int n4)
{
    int i = blockIdx.x * blockDim.x + threadIdx.x;
    if (i >= n4) return;
    float4 v = *(const float4*)&in[(size_t)i * 4];
    __nv_bfloat162 p0 = __floats2bfloat162_rn(v.x, v.y);
    __nv_bfloat162 p1 = __floats2bfloat162_rn(v.z, v.w);
    uint2 o = make_uint2(*(unsigned*)&p0, *(unsigned*)&p1);
    *(uint2*)&out[(size_t)i * 4] = o;
}

// ---------------- weight transpose+convert: f32[K][N] -> bf16[N][K] ----------------
__global__ void transpose_cvt_kernel(const float* __restrict__ in,
                                     __nv_bfloat16* __restrict__ out)
{
    __shared__ float tile[32][33];
    int x = blockIdx.x * 32 + threadIdx.x;
    int y0 = blockIdx.y * 32;
#pragma unroll
    for (int j = 0; j < 32; j += 8)
        tile[threadIdx.y + j][threadIdx.x] = in[(size_t)(y0 + threadIdx.y + j) * DD + x];
    __syncthreads();
    int xo = blockIdx.y * 32 + threadIdx.x;
    int yo = blockIdx.x * 32;
#pragma unroll
    for (int j = 0; j < 32; j += 8)
        out[(size_t)(yo + threadIdx.y + j) * DD + xo] =
            __float2bfloat16(tile[threadIdx.x][threadIdx.y + j]);
}

// ---------------- bf16 tensor-core GEMM with ldmatrix fragments --------------------
// C = A[MxK] @ Bt^T (Bt = [N][K] bf16). MODE 0: C bf16; MODE 1: wp*A, C f32+bias+resid
#define AW 20   // smem row stride in 4B words; rows mod 32 cover all banks

template <int MODE>
__global__ __launch_bounds__(256)
void bgemm_kernel(const __nv_bfloat16* __restrict__ A,
                  const __nv_bfloat16* __restrict__ Bt,
                  void* __restrict__ Cv, int M, int N, int K,
                  const float* __restrict__ bias, const float* __restrict__ resid,
                  const float* __restrict__ wp)
{
    __shared__ unsigned As[2][128 * AW];
    __shared__ unsigned Bs[2][128 * AW];

    const int tid  = threadIdx.x;
    const int lane = tid & 31;
    const int warp = tid >> 5;
    const int g = lane >> 2;
    const int t = lane & 3;
    const int warp_m = warp & 3;
    const int warp_n = warp >> 2;
    const int bm = blockIdx.y * 128;
    const int bn = blockIdx.x * 128;
    const int K2 = K >> 1;

    const int lrow = lane & 15;
    const int lcol = (lane >> 4) << 2;

    const unsigned* Ag = (const unsigned*)A;
    const unsigned* Bg = (const unsigned*)Bt;

    float acc[2][8][4];
#pragma unroll
    for (int mi = 0; mi < 2; mi++)
#pragma unroll
        for (int nt = 0; nt < 8; nt++)
#pragma unroll
            for (int j = 0; j < 4; j++) acc[mi][nt][j] = 0.f;

#define LOAD_STAGE(b, k0)                                                        \
    {                                                                            \
        int kw = (k0) >> 1;                                                      \
        _Pragma("unroll")                                                        \
        for (int i = 0; i < 8; i++) {                                            \
            int idx = tid + 256 * i;                                             \
            int r = idx >> 4, c = idx & 15;                                      \
            unsigned aw = Ag[(size_t)(bm + r) * K2 + kw + c];                    \
            if (MODE == 1) {                                                     \
                int row = bm + r;                                                \
                int bc = row >> 12, s = row & 4095, hh = (k0) >> 6;              \
                float w = wp[((size_t)bc * HD + hh) * SD + s];                   \
                float2 f = __bfloat1622float2(*(__nv_bfloat162*)&aw);            \
                __nv_bfloat162 p = __floats2bfloat162_rn(f.x * w, f.y * w);      \
                aw = *(unsigned*)&p;                                             \
            }                                                                    \
            As[b][r * AW + c] = aw;                                              \
            Bs[b][r * AW + c] = Bg[(size_t)(bn + r) * K2 + kw + c];              \
        }                                                                        \
    }

    LOAD_STAGE(0, 0)
    __syncthreads();

    int buf = 0;
    for (int k0 = 0; k0 < K; k0 += 32) {
        const bool more = (k0 + 32) < K;
        unsigned pa[8], pb[8];
        float pwv[8];
        if (more) {
            int kw = (k0 + 32) >> 1;
#pragma unroll
            for (int i = 0; i < 8; i++) {
                int idx = tid + 256 * i;
                int r = idx >> 4, c = idx & 15;
                pa[i] = Ag[(size_t)(bm + r) * K2 + kw + c];
                pb[i] = Bg[(size_t)(bn + r) * K2 + kw + c];
                if (MODE == 1) {
                    int row = bm + r;
                    int bc = row >> 12, s = row & 4095, hh = (k0 + 32) >> 6;
                    pwv[i] = wp[((size_t)bc * HD + hh) * SD + s];
                }
            }
        }

        // ---- compute: 2 x k16 steps, fragments via ldmatrix ----
#pragma unroll
        for (int s16 = 0; s16 < 2; s16++) {
            const int off = 8 * s16 + lcol;
            unsigned a[2][4];
#pragma unroll
            for (int mi = 0; mi < 2; mi++) {
                int row = warp_m * 32 + 16 * mi + lrow;
                ldsm4(a[mi][0], a[mi][1], a[mi][2], a[mi][3],
                      &As[buf][row * AW + off]);
            }
            unsigned bf[4][4];
#pragma unroll
            for (int nt2 = 0; nt2 < 4; nt2++) {
                int row = warp_n * 64 + 16 * nt2 + lrow;
                ldsm4(bf[nt2][0], bf[nt2][1], bf[nt2][2], bf[nt2][3],
                      &Bs[buf][row * AW + off]);
            }
#pragma unroll
            for (int nt2 = 0; nt2 < 4; nt2++) {
#pragma unroll
                for (int mi = 0; mi < 2; mi++) {
                    mma_bf16(acc[mi][2 * nt2 + 0], a[mi][0], a[mi][1], a[mi][2], a[mi][3],
                             bf[nt2][0], bf[nt2][2]);
                    mma_bf16(acc[mi][2 * nt2 + 1], a[mi][0], a[mi][1], a[mi][2], a[mi][3],
                             bf[nt2][1], bf[nt2][3]);
                }
            }
        }

        if (more) {
            int nb = buf ^ 1;
#pragma unroll
            for (int i = 0; i < 8; i++) {
                int idx = tid + 256 * i;
                int r = idx >> 4, c = idx & 15;
                unsigned aw = pa[i];
                if (MODE == 1) {
                    float2 f = __bfloat1622float2(*(__nv_bfloat162*)&aw);
                    __nv_bfloat162 p = __floats2bfloat162_rn(f.x * pwv[i], f.y * pwv[i]);
                    aw = *(unsigned*)&p;
                }
                As[nb][r * AW + c] = aw;
                Bs[nb][r * AW + c] = pb[i];
            }
            __syncthreads();
            buf = nb;
        }
    }

    // ---- epilogue ----
#pragma unroll
    for (int mi = 0; mi < 2; mi++) {
        int r0 = bm + warp_m * 32 + 16 * mi + g;
#pragma unroll
        for (int nt = 0; nt < 8; nt++) {
            int c = bn + warp_n * 64 + 8 * nt + 2 * t;
            size_t i0 = (size_t)r0 * N + c;
            size_t i1 = (size_t)(r0 + 8) * N + c;
            if (MODE == 1) {
                float* C = (float*)Cv;
                float b0 = bias[c], b1 = bias[c + 1];
                const float2 r0v = *(const float2*)&resid[i0];
                const float2 r1v = *(const float2*)&resid[i1];
                *(float2*)&C[i0] = make_float2(acc[mi][nt][0] + b0 + r0v.x,
                                               acc[mi][nt][1] + b1 + r0v.y);
                *(float2*)&C[i1] = make_float2(acc[mi][nt][2] + b0 + r1v.x,
                                               acc[mi][nt][3] + b1 + r1v.y);
            } else {
                __nv_bfloat16* C = (__nv_bfloat16*)Cv;
                *(__nv_bfloat162*)&C[i0] = __floats2bfloat162_rn(acc[mi][nt][0], acc[mi][nt][1]);
                *(__nv_bfloat162*)&C[i1] = __floats2bfloat162_rn(acc[mi][nt][2], acc[mi][nt][3]);
            }
        }
    }
}

// ---------------- tensor-core attention (unchanged from R9/R10 PASS) ----------------
#define QS_WST 36
#define PS_WST 84
#define KS_WOFF (128 * QS_WST)
#define VT_WOFF (128 * PS_WST)
#define AT2_SMEM_BYTES ((128 * PS_WST + 64 * PS_WST) * 4)

__global__ __launch_bounds__(256)
void attn2_kernel(const __nv_bfloat16* __restrict__ Q,
                  const __nv_bfloat16* __restrict__ Kc,
                  const __nv_bfloat16* __restrict__ Vc,
                  __nv_bfloat16* __restrict__ Ou, float* __restrict__ pooled)
{
    extern __shared__ unsigned smw[];

    const int tid  = threadIdx.x;
    const int lane = tid & 31;
    const int warp = tid >> 5;
    const int g = lane >> 2;
    const int t = lane & 3;
    const int s0 = blockIdx.x * 128;
    const int h  = blockIdx.y;
    const int bc = blockIdx.z;

    {
        const unsigned* Qg = (const unsigned*)(Q + ((size_t)bc * SD + s0) * DD + h * DHD);
#pragma unroll
        for (int i = 0; i < 16; i++) {
            int idx = tid + 256 * i;
            int r = idx >> 5, c = idx & 31;
            smw[r * QS_WST + c] = Qg[(size_t)r * (DD / 2) + c];
        }
        const unsigned* Kg = (const unsigned*)(Kc + ((size_t)bc * ED) * DD + h * DHD);
#pragma unroll
        for (int i = 0; i < 20; i++) {
            int idx = tid + 256 * i;
            int r = idx >> 5, c = idx & 31;
            smw[KS_WOFF + r * QS_WST + c] = Kg[(size_t)r * (DD / 2) + c];
        }
        const unsigned* Vg = (const unsigned*)(Vc + ((size_t)bc * ED) * DD + h * DHD);
        __nv_bfloat16* Vt = (__nv_bfloat16*)(smw + VT_WOFF);
#pragma unroll
        for (int i = 0; i < 20; i++) {
            int idx = tid + 256 * i;
            int e = idx >> 5, d2 = idx & 31;
            unsigned w = Vg[(size_t)e * (DD / 2) + d2];
            __nv_bfloat162 v2 = *(__nv_bfloat162*)&w;
            Vt[(2 * d2) * (2 * PS_WST) + e]     = v2.x;
            Vt[(2 * d2 + 1) * (2 * PS_WST) + e] = v2.y;
        }
    }
    __syncthreads();

    float sc[20][4];
#pragma unroll
    for (int nt = 0; nt < 20; nt++)
#pragma unroll
        for (int j = 0; j < 4; j++) sc[nt][j] = 0.f;

    const int ra = (16 * warp + g) * QS_WST;
    const int rb = (16 * warp + g + 8) * QS_WST;
#pragma unroll
    for (int kk = 0; kk < 4; kk++) {
        unsigned a0 = smw[ra + 8 * kk + t];
        unsigned a1 = smw[rb + 8 * kk + t];
        unsigned a2 = smw[ra + 8 * kk + t + 4];
        unsigned a3 = smw[rb + 8 * kk + t + 4];
#pragma unroll
        for (int nt = 0; nt < 20; nt++) {
            int kb = KS_WOFF + (8 * nt + g) * QS_WST + 8 * kk + t;
            mma_bf16(sc[nt], a0, a1, a2, a3, smw[kb], smw[kb + 4]);
        }
    }

    const float SCALE = 0.125f;
    float m0 = -1e30f, m1 = -1e30f, t0 = 0.f, t1 = 0.f;
#pragma unroll
    for (int nt = 0; nt < 20; nt++) {
        sc[nt][0] *= SCALE; sc[nt][1] *= SCALE;
        sc[nt][2] *= SCALE; sc[nt][3] *= SCALE;
        t0 += sc[nt][0] + sc[nt][1];
        t1 += sc[nt][2] + sc[nt][3];
        m0 = fmaxf(m0, fmaxf(sc[nt][0], sc[nt][1]));
        m1 = fmaxf(m1, fmaxf(sc[nt][2], sc[nt][3]));
    }
#pragma unroll
    for (int off = 1; off <= 2; off <<= 1) {
        m0 = fmaxf(m0, __shfl_xor_sync(0xffffffffu, m0, off));
        m1 = fmaxf(m1, __shfl_xor_sync(0xffffffffu, m1, off));
        t0 += __shfl_xor_sync(0xffffffffu, t0, off);
        t1 += __shfl_xor_sync(0xffffffffu, t1, off);
    }
    if (t == 0) {
        size_t pb = ((size_t)bc * HD + h) * SD + s0 + 16 * warp;
        pooled[pb + g]     = t0 * (1.f / 160.f);
        pooled[pb + g + 8] = t1 * (1.f / 160.f);
    }
    float e0 = 0.f, e1 = 0.f;
#pragma unroll
    for (int nt = 0; nt < 20; nt++) {
        sc[nt][0] = __expf(sc[nt][0] - m0); e0 += sc[nt][0];
        sc[nt][1] = __expf(sc[nt][1] - m0); e0 += sc[nt][1];
        sc[nt][2] = __expf(sc[nt][2] - m1); e1 += sc[nt][2];
        sc[nt][3] = __expf(sc[nt][3] - m1); e1 += sc[nt][3];
    }
#pragma unroll
    for (int off = 1; off <= 2; off <<= 1) {
        e0 += __shfl_xor_sync(0xffffffffu, e0, off);
        e1 += __shfl_xor_sync(0xffffffffu, e1, off);
    }
    const float i0 = 1.f / e0, i1 = 1.f / e1;

    __syncthreads();

    const int pr0 = (16 * warp + g) * PS_WST;
    const int pr1 = (16 * warp + g + 8) * PS_WST;
#pragma unroll
    for (int nt = 0; nt < 20; nt++) {
        __nv_bfloat162 p0 = __floats2bfloat162_rn(sc[nt][0] * i0, sc[nt][1] * i0);
        __nv_bfloat162 p1 = __floats2bfloat162_rn(sc[nt][2] * i1, sc[nt][3] * i1);
        smw[pr0 + 4 * nt + t] = *(unsigned*)&p0;
        smw[pr1 + 4 * nt + t] = *(unsigned*)&p1;
    }
    __syncwarp();

    float o[8][4];
#pragma unroll
    for (int nt = 0; nt < 8; nt++)
#pragma unroll
        for (int j = 0; j < 4; j++) o[nt][j] = 0.f;

#pragma unroll
    for (int kk = 0; kk < 10; kk++) {
        unsigned a0 = smw[pr0 + 8 * kk + t];
        unsigned a1 = smw[pr1 + 8 * kk + t];
        unsigned a2 = smw[pr0 + 8 * kk + t + 4];
        unsigned a3 = smw[pr1 + 8 * kk + t + 4];
#pragma unroll
        for (int nt = 0; nt < 8; nt++) {
            int vb = VT_WOFF + (8 * nt + g) * PS_WST + 8 * kk + t;
            mma_bf16(o[nt], a0, a1, a2, a3, smw[vb], smw[vb + 4]);
        }
    }

    const size_t ob0 = ((size_t)bc * SD + s0 + 16 * warp + g) * DD + h * DHD;
    const size_t ob1 = ob0 + 8 * DD;
#pragma unroll
    for (int nt = 0; nt < 8; nt++) {
        int c = 8 * nt + 2 * t;
        *(__nv_bfloat162*)&Ou[ob0 + c] = __floats2bfloat162_rn(o[nt][0], o[nt][1]);
        *(__nv_bfloat162*)&Ou[ob1 + c] = __floats2bfloat162_rn(o[nt][2], o[nt][3]);
    }
}

// ---------------- component softmax over pooled -> wp ----------------
__global__ void wp_kernel(const float* __restrict__ pooled, float* __restrict__ wp)
{
    int idx = blockIdx.x * blockDim.x + threadIdx.x;
    if (idx >= BD * HD * SD) return;
    int b = idx / (HD * SD);
    int rem = idx % (HD * SD);

    float p[CD];
    float mx = -1e30f;
#pragma unroll
    for (int c = 0; c < CD; c++) {
        p[c] = pooled[(size_t)(c * BD + b) * HD * SD + rem];
        mx = fmaxf(mx, p[c]);
    }
    float se = 0.f;
#pragma unroll
    for (int c = 0; c < CD; c++) {
        p[c] = __expf(p[c] - mx);
        se += p[c];
    }
    float inv = 1.f / se;
#pragma unroll
    for (int c = 0; c < CD; c++)
        wp[(size_t)(c * BD + b) * HD * SD + rem] = p[c] * inv;
}

// ---------------- launch ----------------
extern "C" void kernel_launch(void* const* d_in, const int* in_sizes, int n_in,
                              void* d_out, int out_size)
{
    const float* hidden = (const float*)d_in[0];
    const float* enc    = (const float*)d_in[1];
    const float* Wq     = (const float*)d_in[2];
    const float* Wk     = (const float*)d_in[3];
    const float* Wv     = (const float*)d_in[4];
    const float* Wo     = (const float*)d_in[5];
    const float* bo     = (const float*)d_in[6];
    float* out = (float*)d_out;

    __nv_bfloat16 *pHb, *pEb, *pWqt, *pWkt, *pWvt, *pWot, *pQ, *pK, *pV, *pA;
    float *pPooled, *pWp;
    cudaGetSymbolAddress((void**)&pHb, g_hb);
    cudaGetSymbolAddress((void**)&pEb, g_eb);
    cudaGetSymbolAddress((void**)&pWqt, g_Wqt);
    cudaGetSymbolAddress((void**)&pWkt, g_Wkt);
    cudaGetSymbolAddress((void**)&pWvt, g_Wvt);
    cudaGetSymbolAddress((void**)&pWot, g_Wot);
    cudaGetSymbolAddress((void**)&pQ, g_Qb);
    cudaGetSymbolAddress((void**)&pK, g_Kb);
    cudaGetSymbolAddress((void**)&pV, g_Vb);
    cudaGetSymbolAddress((void**)&pA, g_attnb);
    cudaGetSymbolAddress((void**)&pPooled, g_pooled);
    cudaGetSymbolAddress((void**)&pWp, g_wp);

    // 0) pre-convert activations, pre-transpose weights
    {
        int n4h = BCD * SD * DD / 4;
        cvt_kernel<<<(n4h + 255) / 256, 256>>>(hidden, pHb, n4h);
        int n4e = BCD * ED * DD / 4;
        cvt_kernel<<<(n4e + 255) / 256, 256>>>(enc, pEb, n4e);
        dim3 tg(DD / 32, DD / 32), tb(32, 8);
        transpose_cvt_kernel<<<tg, tb>>>(Wq, pWqt);
        transpose_cvt_kernel<<<tg, tb>>>(Wk, pWkt);
        transpose_cvt_kernel<<<tg, tb>>>(Wv, pWvt);
        transpose_cvt_kernel<<<tg, tb>>>(Wo, pWot);
    }
    // 1) Q = hidden @ Wq -> bf16
    {
        dim3 grid(DD / 128, (BCD * SD) / 128);
        bgemm_kernel<0><<<grid, 256>>>(pHb, pWqt, pQ, BCD * SD, DD, DD,
                                       nullptr, nullptr, nullptr);
    }
    // 2) K, V = enc @ {Wk, Wv} -> bf16
    {
        dim3 grid(DD / 128, (BCD * ED) / 128);
        bgemm_kernel<0><<<grid, 256>>>(pEb, pWkt, pK, BCD * ED, DD, DD,
                                       nullptr, nullptr, nullptr);
        bgemm_kernel<0><<<grid, 256>>>(pEb, pWvt, pV, BCD * ED, DD, DD,
                                       nullptr, nullptr, nullptr);
    }
    // 3) tensor-core attention -> unscaled attn (bf16) + pooled
    {
        cudaFuncSetAttribute(attn2_kernel, cudaFuncAttributeMaxDynamicSharedMemorySize,
                             AT2_SMEM_BYTES);
        dim3 grid(SD / 128, HD, BCD);
        attn2_kernel<<<grid, 256, AT2_SMEM_BYTES>>>(pQ, pK, pV, pA, pPooled);
    }
    // 4) component-softmax weights
    {
        int n = BD * HD * SD;
        wp_kernel<<<(n + 255) / 256, 256>>>(pPooled, pWp);
    }
    // 5) out = (wp .* attn) @ Wo + bo + hidden
    {
        dim3 grid(DD / 128, (BCD * SD) / 128);
        bgemm_kernel<1><<<grid, 256>>>(pA, pWot, out, BCD * SD, DD, DD,
                                       bo, hidden, pWp);
    }
}

// round 17
// speedup vs baseline: 2.5032x; 1.2185x over previous
#include <cuda_runtime.h>
#include <cuda_bf16.h>
#include <math.h>

#define BCD 8
#define SD  4096
#define DD  1024
#define ED  160
#define HD  16
#define DHD 64
#define CD  4
#define BD  2

// ---------------- scratch (static device globals; no allocation) ----------------
__device__ __nv_bfloat16 g_hb[BCD * SD * DD];    // 64 MB  hidden bf16
__device__ __nv_bfloat16 g_eb[BCD * ED * DD];    // 2.5 MB enc bf16
__device__ __nv_bfloat16 g_Wqt[DD * DD];         // 2 MB   Wq^T bf16 [N][K]
__device__ __nv_bfloat16 g_Wkt[DD * DD];
__device__ __nv_bfloat16 g_Wvt[DD * DD];
__device__ __nv_bfloat16 g_Wot[DD * DD];
__device__ __nv_bfloat16 g_Qb[BCD * SD * DD];    // 64 MB
__device__ __nv_bfloat16 g_Kb[BCD * ED * DD];
__device__ __nv_bfloat16 g_Vb[BCD * ED * DD];
__device__ __nv_bfloat16 g_attnb[BCD * SD * DD]; // 64 MB
__device__ float g_pooled[BCD * HD * SD];
__device__ float g_wp[BCD * HD * SD];

__device__ __forceinline__ void mma_bf16(float* c, unsigned a0, unsigned a1,
                                         unsigned a2, unsigned a3,
                                         unsigned b0, unsigned b1) {
    asm volatile(
        "mma.sync.aligned.m16n8k16.row.col.f32.bf16.bf16.f32 "
        "{%0,%1,%2,%3}, {%4,%5,%6,%7}, {%8,%9}, {%0,%1,%2,%3};\n"
        : "+f"(c[0]), "+f"(c[1]), "+f"(c[2]), "+f"(c[3])
        : "r"(a0), "r"(a1), "r"(a2), "r"(a3), "r"(b0), "r"(b1));
}

__device__ __forceinline__ void ldsm4(unsigned& r0, unsigned& r1, unsigned& r2,
                                      unsigned& r3, const void* p) {
    unsigned addr = (unsigned)__cvta_generic_to_shared(p);
    asm volatile("ldmatrix.sync.aligned.m8n8.x4.shared.b16 {%0,%1,%2,%3}, [%4];"
                 : "=r"(r0), "=r"(r1), "=r"(r2), "=r"(r3) : "r"(addr));
}

__device__ __forceinline__ void cpasync16(void* dst, const void* src) {
    unsigned d = (unsigned)__cvta_generic_to_shared(dst);
    asm volatile("cp.async.cg.shared.global [%0], [%1], 16;" :: "r"(d), "l"(src)
                 : "memory");
}
#define CP_COMMIT() asm volatile("cp.async.commit_group;" ::: "memory")
#define CP_WAIT1()  asm volatile("cp.async.wait_group 1;" ::: "memory")
#define CP_WAIT0()  asm volatile("cp.async.wait_group 0;" ::: "memory")

// ---------------- f32 -> bf16 flat convert ----------------
__global__ void cvt_kernel(const float* __restrict__ in, __nv_bfloat16* __restrict__ out,
                           int n4)
{
    int i = blockIdx.x * blockDim.x + threadIdx.x;
    if (i >= n4) return;
    float4 v = *(const float4*)&in[(size_t)i * 4];
    __nv_bfloat162 p0 = __floats2bfloat162_rn(v.x, v.y);
    __nv_bfloat162 p1 = __floats2bfloat162_rn(v.z, v.w);
    uint2 o = make_uint2(*(unsigned*)&p0, *(unsigned*)&p1);
    *(uint2*)&out[(size_t)i * 4] = o;
}

// ---------------- weight transpose+convert: f32[K][N] -> bf16[N][K] ----------------
__global__ void transpose_cvt_kernel(const float* __restrict__ in,
                                     __nv_bfloat16* __restrict__ out)
{
    __shared__ float tile[32][33];
    int x = blockIdx.x * 32 + threadIdx.x;
    int y0 = blockIdx.y * 32;
#pragma unroll
    for (int j = 0; j < 32; j += 8)
        tile[threadIdx.y + j][threadIdx.x] = in[(size_t)(y0 + threadIdx.y + j) * DD + x];
    __syncthreads();
    int xo = blockIdx.y * 32 + threadIdx.x;
    int yo = blockIdx.x * 32;
#pragma unroll
    for (int j = 0; j < 32; j += 8)
        out[(size_t)(yo + threadIdx.y + j) * DD + xo] =
            __float2bfloat16(tile[threadIdx.x][threadIdx.y + j]);
}

// ---------------- wp in-place prescale of attn buffer -----------------------------
// attn[bc][s][h*64+d] *= wp[bc][h][s]; 8 bf16 per thread (same h per uint4)
__global__ void wpscale_kernel(__nv_bfloat16* __restrict__ attn,
                               const float* __restrict__ wp)
{
    size_t i8 = (size_t)blockIdx.x * blockDim.x + threadIdx.x;
    const size_t n8 = (size_t)BCD * SD * DD / 8;
    if (i8 >= n8) return;
    size_t flat = i8 * 8;
    int bc = (int)(flat >> 22);
    int rem = (int)(flat & ((1u << 22) - 1));
    int s = rem >> 10;
    int h = (rem & 1023) >> 6;
    float w = wp[((size_t)bc * HD + h) * SD + s];
    uint4 v = *(uint4*)&attn[flat];
    unsigned* pv = (unsigned*)&v;
#pragma unroll
    for (int j = 0; j < 4; j++) {
        float2 f = __bfloat1622float2(*(__nv_bfloat162*)&pv[j]);
        __nv_bfloat162 p = __floats2bfloat162_rn(f.x * w, f.y * w);
        pv[j] = *(unsigned*)&p;
    }
    *(uint4*)&attn[flat] = v;
}

// ---------------- bf16 tensor-core GEMM: cp.async 3-stage + ldmatrix --------------
// C = A[MxK] @ Bt^T (Bt = [N][K] bf16). MODE 0: C bf16; MODE 1: C f32 + bias + resid
#define AW 20                      // smem row stride in words (16 data + 4 pad)
#define TILE_W (128 * AW)          // words per tile (A or B) incl. pad
#define BG_STAGES 3
#define BG_SMEM_BYTES (BG_STAGES * 2 * TILE_W * 4)   // 61440 B

template <int MODE>
__global__ __launch_bounds__(256)
void bgemm_kernel(const __nv_bfloat16* __restrict__ A,
                  const __nv_bfloat16* __restrict__ Bt,
                  void* __restrict__ Cv, int M, int N, int K,
                  const float* __restrict__ bias, const float* __restrict__ resid)
{
    extern __shared__ unsigned sm[];
    unsigned* AsB = sm;                      // [BG_STAGES][TILE_W]
    unsigned* BsB = sm + BG_STAGES * TILE_W;

    const int tid  = threadIdx.x;
    const int lane = tid & 31;
    const int warp = tid >> 5;
    const int g = lane >> 2;
    const int t = lane & 3;
    const int warp_m = warp & 3;
    const int warp_n = warp >> 2;
    const int bm = blockIdx.y * 128;
    const int bn = blockIdx.x * 128;
    const int K2 = K >> 1;                   // words per gmem row

    const int lrow = lane & 15;
    const int lcol = (lane >> 4) << 2;

    const unsigned* Ag = (const unsigned*)A;
    const unsigned* Bg = (const unsigned*)Bt;

    // per-thread copy mapping: 2 chunks of 16B for A, 2 for B per stage
    const int ch0 = tid, ch1 = tid + 256;    // chunk ids 0..511
    const int r0c = ch0 >> 2, w0c = (ch0 & 3) * 4;
    const int r1c = ch1 >> 2, w1c = (ch1 & 3) * 4;

    float acc[2][8][4];
#pragma unroll
    for (int mi = 0; mi < 2; mi++)
#pragma unroll
        for (int nt = 0; nt < 8; nt++)
#pragma unroll
            for (int j = 0; j < 4; j++) acc[mi][nt][j] = 0.f;

#define ISSUE_STAGE(st, k0)                                                       \
    {                                                                             \
        int kw = (k0) >> 1;                                                       \
        cpasync16(&AsB[(st) * TILE_W + r0c * AW + w0c],                           \
                  &Ag[(size_t)(bm + r0c) * K2 + kw + w0c]);                       \
        cpasync16(&AsB[(st) * TILE_W + r1c * AW + w1c],                           \
                  &Ag[(size_t)(bm + r1c) * K2 + kw + w1c]);                       \
        cpasync16(&BsB[(st) * TILE_W + r0c * AW + w0c],                           \
                  &Bg[(size_t)(bn + r0c) * K2 + kw + w0c]);                       \
        cpasync16(&BsB[(st) * TILE_W + r1c * AW + w1c],                           \
                  &Bg[(size_t)(bn + r1c) * K2 + kw + w1c]);                       \
        CP_COMMIT();                                                              \
    }

    ISSUE_STAGE(0, 0)
    ISSUE_STAGE(1, 32)

    int buf = 0;
    for (int k0 = 0; k0 < K; k0 += 32) {
        CP_WAIT1();            // stage for k0 complete (<=1 group outstanding)
        __syncthreads();       // all warps done with buffer (buf+2)%3's compute
        if (k0 + 64 < K) {
            int nst = buf + 2; if (nst >= BG_STAGES) nst -= BG_STAGES;
            ISSUE_STAGE(nst, k0 + 64)
        }

        const unsigned* As = AsB + buf * TILE_W;
        const unsigned* Bs = BsB + buf * TILE_W;

#pragma unroll
        for (int s16 = 0; s16 < 2; s16++) {
            const int off = 8 * s16 + lcol;
            unsigned a[2][4];
#pragma unroll
            for (int mi = 0; mi < 2; mi++) {
                int row = warp_m * 32 + 16 * mi + lrow;
                ldsm4(a[mi][0], a[mi][1], a[mi][2], a[mi][3], &As[row * AW + off]);
            }
            unsigned bf[4][4];
#pragma unroll
            for (int nt2 = 0; nt2 < 4; nt2++) {
                int row = warp_n * 64 + 16 * nt2 + lrow;
                ldsm4(bf[nt2][0], bf[nt2][1], bf[nt2][2], bf[nt2][3],
                      &Bs[row * AW + off]);
            }
#pragma unroll
            for (int nt2 = 0; nt2 < 4; nt2++) {
#pragma unroll
                for (int mi = 0; mi < 2; mi++) {
                    mma_bf16(acc[mi][2 * nt2 + 0], a[mi][0], a[mi][1], a[mi][2], a[mi][3],
                             bf[nt2][0], bf[nt2][2]);
                    mma_bf16(acc[mi][2 * nt2 + 1], a[mi][0], a[mi][1], a[mi][2], a[mi][3],
                             bf[nt2][1], bf[nt2][3]);
                }
            }
        }

        buf++; if (buf >= BG_STAGES) buf = 0;
    }
    CP_WAIT0();

    // ---- epilogue ----
#pragma unroll
    for (int mi = 0; mi < 2; mi++) {
        int r0 = bm + warp_m * 32 + 16 * mi + g;
#pragma unroll
        for (int nt = 0; nt < 8; nt++) {
            int c = bn + warp_n * 64 + 8 * nt + 2 * t;
            size_t i0 = (size_t)r0 * N + c;
            size_t i1 = (size_t)(r0 + 8) * N + c;
            if (MODE == 1) {
                float* C = (float*)Cv;
                float b0 = bias[c], b1 = bias[c + 1];
                const float2 r0v = *(const float2*)&resid[i0];
                const float2 r1v = *(const float2*)&resid[i1];
                *(float2*)&C[i0] = make_float2(acc[mi][nt][0] + b0 + r0v.x,
                                               acc[mi][nt][1] + b1 + r0v.y);
                *(float2*)&C[i1] = make_float2(acc[mi][nt][2] + b0 + r1v.x,
                                               acc[mi][nt][3] + b1 + r1v.y);
            } else {
                __nv_bfloat16* C = (__nv_bfloat16*)Cv;
                *(__nv_bfloat162*)&C[i0] = __floats2bfloat162_rn(acc[mi][nt][0], acc[mi][nt][1]);
                *(__nv_bfloat162*)&C[i1] = __floats2bfloat162_rn(acc[mi][nt][2], acc[mi][nt][3]);
            }
        }
    }
}

// ---------------- tensor-core attention (unchanged from R9/R10/R16 PASS) -----------
#define QS_WST 36
#define PS_WST 84
#define KS_WOFF (128 * QS_WST)
#define VT_WOFF (128 * PS_WST)
#define AT2_SMEM_BYTES ((128 * PS_WST + 64 * PS_WST) * 4)

__global__ __launch_bounds__(256)
void attn2_kernel(const __nv_bfloat16* __restrict__ Q,
                  const __nv_bfloat16* __restrict__ Kc,
                  const __nv_bfloat16* __restrict__ Vc,
                  __nv_bfloat16* __restrict__ Ou, float* __restrict__ pooled)
{
    extern __shared__ unsigned smw[];

    const int tid  = threadIdx.x;
    const int lane = tid & 31;
    const int warp = tid >> 5;
    const int g = lane >> 2;
    const int t = lane & 3;
    const int s0 = blockIdx.x * 128;
    const int h  = blockIdx.y;
    const int bc = blockIdx.z;

    {
        const unsigned* Qg = (const unsigned*)(Q + ((size_t)bc * SD + s0) * DD + h * DHD);
#pragma unroll
        for (int i = 0; i < 16; i++) {
            int idx = tid + 256 * i;
            int r = idx >> 5, c = idx & 31;
            smw[r * QS_WST + c] = Qg[(size_t)r * (DD / 2) + c];
        }
        const unsigned* Kg = (const unsigned*)(Kc + ((size_t)bc * ED) * DD + h * DHD);
#pragma unroll
        for (int i = 0; i < 20; i++) {
            int idx = tid + 256 * i;
            int r = idx >> 5, c = idx & 31;
            smw[KS_WOFF + r * QS_WST + c] = Kg[(size_t)r * (DD / 2) + c];
        }
        const unsigned* Vg = (const unsigned*)(Vc + ((size_t)bc * ED) * DD + h * DHD);
        __nv_bfloat16* Vt = (__nv_bfloat16*)(smw + VT_WOFF);
#pragma unroll
        for (int i = 0; i < 20; i++) {
            int idx = tid + 256 * i;
            int e = idx >> 5, d2 = idx & 31;
            unsigned w = Vg[(size_t)e * (DD / 2) + d2];
            __nv_bfloat162 v2 = *(__nv_bfloat162*)&w;
            Vt[(2 * d2) * (2 * PS_WST) + e]     = v2.x;
            Vt[(2 * d2 + 1) * (2 * PS_WST) + e] = v2.y;
        }
    }
    __syncthreads();

    float sc[20][4];
#pragma unroll
    for (int nt = 0; nt < 20; nt++)
#pragma unroll
        for (int j = 0; j < 4; j++) sc[nt][j] = 0.f;

    const int ra = (16 * warp + g) * QS_WST;
    const int rb = (16 * warp + g + 8) * QS_WST;
#pragma unroll
    for (int kk = 0; kk < 4; kk++) {
        unsigned a0 = smw[ra + 8 * kk + t];
        unsigned a1 = smw[rb + 8 * kk + t];
        unsigned a2 = smw[ra + 8 * kk + t + 4];
        unsigned a3 = smw[rb + 8 * kk + t + 4];
#pragma unroll
        for (int nt = 0; nt < 20; nt++) {
            int kb = KS_WOFF + (8 * nt + g) * QS_WST + 8 * kk + t;
            mma_bf16(sc[nt], a0, a1, a2, a3, smw[kb], smw[kb + 4]);
        }
    }

    const float SCALE = 0.125f;
    float m0 = -1e30f, m1 = -1e30f, t0 = 0.f, t1 = 0.f;
#pragma unroll
    for (int nt = 0; nt < 20; nt++) {
        sc[nt][0] *= SCALE; sc[nt][1] *= SCALE;
        sc[nt][2] *= SCALE; sc[nt][3] *= SCALE;
        t0 += sc[nt][0] + sc[nt][1];
        t1 += sc[nt][2] + sc[nt][3];
        m0 = fmaxf(m0, fmaxf(sc[nt][0], sc[nt][1]));
        m1 = fmaxf(m1, fmaxf(sc[nt][2], sc[nt][3]));
    }
#pragma unroll
    for (int off = 1; off <= 2; off <<= 1) {
        m0 = fmaxf(m0, __shfl_xor_sync(0xffffffffu, m0, off));
        m1 = fmaxf(m1, __shfl_xor_sync(0xffffffffu, m1, off));
        t0 += __shfl_xor_sync(0xffffffffu, t0, off);
        t1 += __shfl_xor_sync(0xffffffffu, t1, off);
    }
    if (t == 0) {
        size_t pb = ((size_t)bc * HD + h) * SD + s0 + 16 * warp;
        pooled[pb + g]     = t0 * (1.f / 160.f);
        pooled[pb + g + 8] = t1 * (1.f / 160.f);
    }
    float e0 = 0.f, e1 = 0.f;
#pragma unroll
    for (int nt = 0; nt < 20; nt++) {
        sc[nt][0] = __expf(sc[nt][0] - m0); e0 += sc[nt][0];
        sc[nt][1] = __expf(sc[nt][1] - m0); e0 += sc[nt][1];
        sc[nt][2] = __expf(sc[nt][2] - m1); e1 += sc[nt][2];
        sc[nt][3] = __expf(sc[nt][3] - m1); e1 += sc[nt][3];
    }
#pragma unroll
    for (int off = 1; off <= 2; off <<= 1) {
        e0 += __shfl_xor_sync(0xffffffffu, e0, off);
        e1 += __shfl_xor_sync(0xffffffffu, e1, off);
    }
    const float i0 = 1.f / e0, i1 = 1.f / e1;

    __syncthreads();

    const int pr0 = (16 * warp + g) * PS_WST;
    const int pr1 = (16 * warp + g + 8) * PS_WST;
#pragma unroll
    for (int nt = 0; nt < 20; nt++) {
        __nv_bfloat162 p0 = __floats2bfloat162_rn(sc[nt][0] * i0, sc[nt][1] * i0);
        __nv_bfloat162 p1 = __floats2bfloat162_rn(sc[nt][2] * i1, sc[nt][3] * i1);
        smw[pr0 + 4 * nt + t] = *(unsigned*)&p0;
        smw[pr1 + 4 * nt + t] = *(unsigned*)&p1;
    }
    __syncwarp();

    float o[8][4];
#pragma unroll
    for (int nt = 0; nt < 8; nt++)
#pragma unroll
        for (int j = 0; j < 4; j++) o[nt][j] = 0.f;

#pragma unroll
    for (int kk = 0; kk < 10; kk++) {
        unsigned a0 = smw[pr0 + 8 * kk + t];
        unsigned a1 = smw[pr1 + 8 * kk + t];
        unsigned a2 = smw[pr0 + 8 * kk + t + 4];
        unsigned a3 = smw[pr1 + 8 * kk + t + 4];
#pragma unroll
        for (int nt = 0; nt < 8; nt++) {
            int vb = VT_WOFF + (8 * nt + g) * PS_WST + 8 * kk + t;
            mma_bf16(o[nt], a0, a1, a2, a3, smw[vb], smw[vb + 4]);
        }
    }

    const size_t ob0 = ((size_t)bc * SD + s0 + 16 * warp + g) * DD + h * DHD;
    const size_t ob1 = ob0 + 8 * DD;
#pragma unroll
    for (int nt = 0; nt < 8; nt++) {
        int c = 8 * nt + 2 * t;
        *(__nv_bfloat162*)&Ou[ob0 + c] = __floats2bfloat162_rn(o[nt][0], o[nt][1]);
        *(__nv_bfloat162*)&Ou[ob1 + c] = __floats2bfloat162_rn(o[nt][2], o[nt][3]);
    }
}

// ---------------- component softmax over pooled -> wp ----------------
__global__ void wp_kernel(const float* __restrict__ pooled, float* __restrict__ wp)
{
    int idx = blockIdx.x * blockDim.x + threadIdx.x;
    if (idx >= BD * HD * SD) return;
    int b = idx / (HD * SD);
    int rem = idx % (HD * SD);

    float p[CD];
    float mx = -1e30f;
#pragma unroll
    for (int c = 0; c < CD; c++) {
        p[c] = pooled[(size_t)(c * BD + b) * HD * SD + rem];
        mx = fmaxf(mx, p[c]);
    }
    float se = 0.f;
#pragma unroll
    for (int c = 0; c < CD; c++) {
        p[c] = __expf(p[c] - mx);
        se += p[c];
    }
    float inv = 1.f / se;
#pragma unroll
    for (int c = 0; c < CD; c++)
        wp[(size_t)(c * BD + b) * HD * SD + rem] = p[c] * inv;
}

// ---------------- launch ----------------
extern "C" void kernel_launch(void* const* d_in, const int* in_sizes, int n_in,
                              void* d_out, int out_size)
{
    const float* hidden = (const float*)d_in[0];
    const float* enc    = (const float*)d_in[1];
    const float* Wq     = (const float*)d_in[2];
    const float* Wk     = (const float*)d_in[3];
    const float* Wv     = (const float*)d_in[4];
    const float* Wo     = (const float*)d_in[5];
    const float* bo     = (const float*)d_in[6];
    float* out = (float*)d_out;

    __nv_bfloat16 *pHb, *pEb, *pWqt, *pWkt, *pWvt, *pWot, *pQ, *pK, *pV, *pA;
    float *pPooled, *pWp;
    cudaGetSymbolAddress((void**)&pHb, g_hb);
    cudaGetSymbolAddress((void**)&pEb, g_eb);
    cudaGetSymbolAddress((void**)&pWqt, g_Wqt);
    cudaGetSymbolAddress((void**)&pWkt, g_Wkt);
    cudaGetSymbolAddress((void**)&pWvt, g_Wvt);
    cudaGetSymbolAddress((void**)&pWot, g_Wot);
    cudaGetSymbolAddress((void**)&pQ, g_Qb);
    cudaGetSymbolAddress((void**)&pK, g_Kb);
    cudaGetSymbolAddress((void**)&pV, g_Vb);
    cudaGetSymbolAddress((void**)&pA, g_attnb);
    cudaGetSymbolAddress((void**)&pPooled, g_pooled);
    cudaGetSymbolAddress((void**)&pWp, g_wp);

    cudaFuncSetAttribute(bgemm_kernel<0>, cudaFuncAttributeMaxDynamicSharedMemorySize,
                         BG_SMEM_BYTES);
    cudaFuncSetAttribute(bgemm_kernel<1>, cudaFuncAttributeMaxDynamicSharedMemorySize,
                         BG_SMEM_BYTES);

    // 0) pre-convert activations, pre-transpose weights
    {
        int n4h = BCD * SD * DD / 4;
        cvt_kernel<<<(n4h + 255) / 256, 256>>>(hidden, pHb, n4h);
        int n4e = BCD * ED * DD / 4;
        cvt_kernel<<<(n4e + 255) / 256, 256>>>(enc, pEb, n4e);
        dim3 tg(DD / 32, DD / 32), tb(32, 8);
        transpose_cvt_kernel<<<tg, tb>>>(Wq, pWqt);
        transpose_cvt_kernel<<<tg, tb>>>(Wk, pWkt);
        transpose_cvt_kernel<<<tg, tb>>>(Wv, pWvt);
        transpose_cvt_kernel<<<tg, tb>>>(Wo, pWot);
    }
    // 1) Q = hidden @ Wq -> bf16
    {
        dim3 grid(DD / 128, (BCD * SD) / 128);
        bgemm_kernel<0><<<grid, 256, BG_SMEM_BYTES>>>(pHb, pWqt, pQ, BCD * SD, DD, DD,
                                                      nullptr, nullptr);
    }
    // 2) K, V = enc @ {Wk, Wv} -> bf16
    {
        dim3 grid(DD / 128, (BCD * ED) / 128);
        bgemm_kernel<0><<<grid, 256, BG_SMEM_BYTES>>>(pEb, pWkt, pK, BCD * ED, DD, DD,
                                                      nullptr, nullptr);
        bgemm_kernel<0><<<grid, 256, BG_SMEM_BYTES>>>(pEb, pWvt, pV, BCD * ED, DD, DD,
                                                      nullptr, nullptr);
    }
    // 3) tensor-core attention -> unscaled attn (bf16) + pooled
    {
        cudaFuncSetAttribute(attn2_kernel, cudaFuncAttributeMaxDynamicSharedMemorySize,
                             AT2_SMEM_BYTES);
        dim3 grid(SD / 128, HD, BCD);
        attn2_kernel<<<grid, 256, AT2_SMEM_BYTES>>>(pQ, pK, pV, pA, pPooled);
    }
    // 4) component-softmax weights + in-place wp prescale of attn
    {
        int n = BD * HD * SD;
        wp_kernel<<<(n + 255) / 256, 256>>>(pPooled, pWp);
        size_t n8 = (size_t)BCD * SD * DD / 8;
        wpscale_kernel<<<(unsigned)((n8 + 255) / 256), 256>>>(pA, pWp);
    }
    // 5) out = attn_scaled @ Wo + bo + hidden
    {
        dim3 grid(DD / 128, (BCD * SD) / 128);
        bgemm_kernel<1><<<grid, 256, BG_SMEM_BYTES>>>(pA, pWot, out, BCD * SD, DD, DD,
                                                      bo, hidden);
    }
}